// round 3
// baseline (speedup 1.0000x reference)
#include <cuda_runtime.h>
#include <math.h>

#define BATCH 4
#define SEQ   2048
#define DM    1024
#define NH    16
#define DKH   64
#define MROWS (BATCH*SEQ)   // 8192

// Scratch (device globals: allocation-free per harness rules)
__device__ float g_Qp[MROWS*DM];
__device__ float g_Kp[MROWS*DM];
__device__ float g_Vp[MROWS*DM];
__device__ float g_Op[MROWS*DM];

// C[m,n] = sum_k A[m,k] * W[n,k] + bias[n]   (torch Linear: x @ W^T + b)
// Tiles: BM=BN=64, BK=16, 256 threads, 4x4 per thread.
__global__ __launch_bounds__(256) void gemm_bias_nt(
    const float* __restrict__ A, const float* __restrict__ W,
    const float* __restrict__ bias, float* __restrict__ C,
    int M, int N, int K)
{
    __shared__ float As[16][64];
    __shared__ float Bs[16][64];
    const int tid = threadIdx.x;
    const int tx = tid & 15;        // 0..15
    const int ty = tid >> 4;        // 0..15
    const int m0 = blockIdx.y * 64;
    const int n0 = blockIdx.x * 64;

    float acc[4][4] = {};

    const int lrow = tid >> 2;        // 0..63
    const int lcol = (tid & 3) * 4;   // 0,4,8,12

    for (int k0 = 0; k0 < K; k0 += 16) {
        const float* Ap = A + (size_t)(m0 + lrow) * K + k0 + lcol;
        const float* Wp = W + (size_t)(n0 + lrow) * K + k0 + lcol;
        #pragma unroll
        for (int r = 0; r < 4; r++) As[lcol + r][lrow] = Ap[r];
        #pragma unroll
        for (int r = 0; r < 4; r++) Bs[lcol + r][lrow] = Wp[r];
        __syncthreads();

        #pragma unroll
        for (int kk = 0; kk < 16; kk++) {
            float a[4], b[4];
            #pragma unroll
            for (int i = 0; i < 4; i++) a[i] = As[kk][ty * 4 + i];
            #pragma unroll
            for (int j = 0; j < 4; j++) b[j] = Bs[kk][tx * 4 + j];
            #pragma unroll
            for (int i = 0; i < 4; i++)
                #pragma unroll
                for (int j = 0; j < 4; j++)
                    acc[i][j] = fmaf(a[i], b[j], acc[i][j]);
        }
        __syncthreads();
    }

    #pragma unroll
    for (int i = 0; i < 4; i++) {
        const int m = m0 + ty * 4 + i;
        #pragma unroll
        for (int j = 0; j < 4; j++) {
            const int n = n0 + tx * 4 + j;
            C[(size_t)m * N + n] = acc[i][j] + bias[n];
        }
    }
}

// Flash attention, fp32, causal. One block = 64 query rows of one (b,h).
// One thread = one query row; online softmax; BK=32 key tile in smem.
__global__ __launch_bounds__(64) void attn_kernel(
    const float* __restrict__ Qp, const float* __restrict__ Kp,
    const float* __restrict__ Vp, float* __restrict__ Op)
{
    __shared__ float Ks[32][64];
    __shared__ float Vs[32][64];

    const int tid = threadIdx.x;
    const int qt = blockIdx.x;     // 0..31
    const int h  = blockIdx.y;     // 0..15
    const int b  = blockIdx.z;     // 0..3
    const int t  = qt * 64 + tid;  // global query index within sequence

    const float scale = 0.125f;    // 1/sqrt(64)

    float qreg[64];
    {
        const float* qptr = Qp + ((size_t)(b * SEQ + t)) * DM + h * DKH;
        #pragma unroll
        for (int d = 0; d < 64; d++) qreg[d] = qptr[d] * scale;
    }

    float acc[64];
    #pragma unroll
    for (int d = 0; d < 64; d++) acc[d] = 0.f;
    float mrun = -1e30f, lrun = 0.f;

    const int nkt = 2 * qt + 2;   // key tiles of 32 covering [0, qt*64+64)

    for (int kt = 0; kt < nkt; kt++) {
        const int j0 = kt * 32;
        // cooperative load: row r, col tid (coalesced)
        #pragma unroll
        for (int r = 0; r < 32; r++) {
            const size_t src = ((size_t)(b * SEQ + j0 + r)) * DM + h * DKH + tid;
            Ks[r][tid] = Kp[src];
            Vs[r][tid] = Vp[src];
        }
        __syncthreads();

        float s[32];
        #pragma unroll
        for (int j = 0; j < 32; j++) {
            float d0 = 0.f;
            #pragma unroll
            for (int d = 0; d < 64; d++) d0 = fmaf(qreg[d], Ks[j][d], d0);
            s[j] = (j0 + j <= t) ? d0 : -1e30f;
        }

        float mnew = mrun;
        #pragma unroll
        for (int j = 0; j < 32; j++) mnew = fmaxf(mnew, s[j]);

        const float corr = __expf(mrun - mnew);
        lrun *= corr;
        #pragma unroll
        for (int d = 0; d < 64; d++) acc[d] *= corr;

        #pragma unroll
        for (int j = 0; j < 32; j++) {
            const float p = __expf(s[j] - mnew);
            lrun += p;
            #pragma unroll
            for (int d = 0; d < 64; d++) acc[d] = fmaf(p, Vs[j][d], acc[d]);
        }
        mrun = mnew;
        __syncthreads();
    }

    const float inv = 1.f / lrun;
    float* optr = Op + ((size_t)(b * SEQ + t)) * DM + h * DKH;
    #pragma unroll
    for (int d = 0; d < 64; d++) optr[d] = acc[d] * inv;
}

extern "C" void kernel_launch(void* const* d_in, const int* in_sizes, int n_in,
                              void* d_out, int out_size)
{
    const float* q   = (const float*)d_in[0];
    const float* k   = (const float*)d_in[1];
    const float* v   = (const float*)d_in[2];
    // d_in[3] is the causal mask (tril) — computed analytically in-kernel.
    const float* w_q = (const float*)d_in[4];
    const float* b_q = (const float*)d_in[5];
    const float* w_k = (const float*)d_in[6];
    const float* b_k = (const float*)d_in[7];
    const float* w_v = (const float*)d_in[8];
    const float* b_v = (const float*)d_in[9];
    const float* w_o = (const float*)d_in[10];
    const float* b_o = (const float*)d_in[11];
    float* out = (float*)d_out;

    float *Qp, *Kp, *Vp, *Op;
    cudaGetSymbolAddress((void**)&Qp, g_Qp);
    cudaGetSymbolAddress((void**)&Kp, g_Kp);
    cudaGetSymbolAddress((void**)&Vp, g_Vp);
    cudaGetSymbolAddress((void**)&Op, g_Op);

    dim3 ggrid(DM / 64, MROWS / 64);   // (16, 128)
    gemm_bias_nt<<<ggrid, 256>>>(q, w_q, b_q, Qp, MROWS, DM, DM);
    gemm_bias_nt<<<ggrid, 256>>>(k, w_k, b_k, Kp, MROWS, DM, DM);
    gemm_bias_nt<<<ggrid, 256>>>(v, w_v, b_v, Vp, MROWS, DM, DM);

    dim3 agrid(SEQ / 64, NH, BATCH);   // (32, 16, 4)
    attn_kernel<<<agrid, 64>>>(Qp, Kp, Vp, Op);

    gemm_bias_nt<<<ggrid, 256>>>(Op, w_o, b_o, out, MROWS, DM, DM);
}

// round 4
// speedup vs baseline: 2.6552x; 2.6552x over previous
#include <cuda_runtime.h>
#include <math.h>

#define BATCH 4
#define SEQ   2048
#define DM    1024
#define NH    16
#define DKH   64
#define MROWS (BATCH*SEQ)   // 8192

// Scratch (device globals: allocation-free per harness rules)
__device__ float g_Qp[MROWS*DM];
__device__ float g_Kp[MROWS*DM];
__device__ float g_Vp[MROWS*DM];
__device__ float g_Op[MROWS*DM];

__device__ __forceinline__ unsigned f2tf(float x){
    unsigned u; asm("cvt.rna.tf32.f32 %0, %1;" : "=r"(u) : "f"(x)); return u;
}
__device__ __forceinline__ void mma8(float c[4], const unsigned a[4], const unsigned b[2]){
    asm volatile("mma.sync.aligned.m16n8k8.row.col.f32.tf32.tf32.f32 "
        "{%0,%1,%2,%3},{%4,%5,%6,%7},{%8,%9},{%0,%1,%2,%3};\n"
        : "+f"(c[0]),"+f"(c[1]),"+f"(c[2]),"+f"(c[3])
        : "r"(a[0]),"r"(a[1]),"r"(a[2]),"r"(a[3]),"r"(b[0]),"r"(b[1]));
}

// ---------------------------------------------------------------------------
// 3xTF32 GEMM:  C[m,n] = sum_k A[m,k]*W[n,k] + bias[n]   (both K-major)
// 128x128x16 tiles, 256 threads, 8 warps (64x32 each), double-buffered smem.
// ---------------------------------------------------------------------------
#define GSTR 20
#define GTILE (128*GSTR)

__device__ __forceinline__ void stash4(float* hi, float* lo, float4 v){
    float hx = __uint_as_float(f2tf(v.x));
    float hy = __uint_as_float(f2tf(v.y));
    float hz = __uint_as_float(f2tf(v.z));
    float hw = __uint_as_float(f2tf(v.w));
    float4 H = {hx, hy, hz, hw};
    float4 L = {__uint_as_float(f2tf(v.x - hx)),
                __uint_as_float(f2tf(v.y - hy)),
                __uint_as_float(f2tf(v.z - hz)),
                __uint_as_float(f2tf(v.w - hw))};
    *(float4*)hi = H;
    *(float4*)lo = L;
}

__global__ __launch_bounds__(256, 2) void gemm3_bias(
    const float* __restrict__ A, const float* __restrict__ W,
    const float* __restrict__ bias, float* __restrict__ C,
    int M, int N, int K)
{
    extern __shared__ float sm[];   // [2 stages][Ah|Al|Bh|Bl][128][GSTR]

    const int tid  = threadIdx.x;
    const int warp = tid >> 5, lane = tid & 31;
    const int g = lane >> 2, t4 = lane & 3;
    const int warpM = (warp >> 2) * 64;
    const int warpN = (warp & 3) * 32;
    const int m0 = blockIdx.y * 128, n0 = blockIdx.x * 128;

    const int crow = tid >> 1;           // 0..127
    const int ccol = (tid & 1) * 8;      // 0 or 8

    const float* Aptr = A + (size_t)(m0 + crow) * K + ccol;
    const float* Wptr = W + (size_t)(n0 + crow) * K + ccol;

    float acc[4][4][4];
    #pragma unroll
    for (int i=0;i<4;i++)
        #pragma unroll
        for (int j=0;j<4;j++)
            #pragma unroll
            for (int c=0;c<4;c++) acc[i][j][c] = 0.f;

    const int KT = K >> 4;

    // prologue: tile 0 -> stage 0
    float4 ra0 = *(const float4*)(Aptr);
    float4 ra1 = *(const float4*)(Aptr + 4);
    float4 rb0 = *(const float4*)(Wptr);
    float4 rb1 = *(const float4*)(Wptr + 4);
    {
        float* st = sm;
        stash4(st +            crow*GSTR + ccol,     st +   GTILE + crow*GSTR + ccol,     ra0);
        stash4(st +            crow*GSTR + ccol + 4, st +   GTILE + crow*GSTR + ccol + 4, ra1);
        stash4(st + 2*GTILE +  crow*GSTR + ccol,     st + 3*GTILE + crow*GSTR + ccol,     rb0);
        stash4(st + 2*GTILE +  crow*GSTR + ccol + 4, st + 3*GTILE + crow*GSTR + ccol + 4, rb1);
    }
    __syncthreads();

    for (int kt = 0; kt < KT; kt++) {
        const float* sa = sm + (kt & 1) * (4*GTILE);
        const float* sb = sa + 2*GTILE;
        const bool pf = (kt + 1 < KT);
        if (pf) {
            const float* Ap = Aptr + (kt+1)*16;
            const float* Wp = Wptr + (kt+1)*16;
            ra0 = *(const float4*)(Ap);
            ra1 = *(const float4*)(Ap + 4);
            rb0 = *(const float4*)(Wp);
            rb1 = *(const float4*)(Wp + 4);
        }

        #pragma unroll
        for (int kk = 0; kk < 2; kk++) {
            const int ko = kk * 8;
            unsigned bh[4][2], bl[4][2];
            #pragma unroll
            for (int nt = 0; nt < 4; nt++) {
                const int n = warpN + nt*8 + g;
                bh[nt][0] = __float_as_uint(sb[n*GSTR + ko + t4]);
                bh[nt][1] = __float_as_uint(sb[n*GSTR + ko + t4 + 4]);
                bl[nt][0] = __float_as_uint(sb[GTILE + n*GSTR + ko + t4]);
                bl[nt][1] = __float_as_uint(sb[GTILE + n*GSTR + ko + t4 + 4]);
            }
            #pragma unroll
            for (int mt = 0; mt < 4; mt++) {
                const int m = warpM + mt*16;
                unsigned ah[4], al[4];
                ah[0] = __float_as_uint(sa[(m+g  )*GSTR + ko + t4]);
                ah[1] = __float_as_uint(sa[(m+g+8)*GSTR + ko + t4]);
                ah[2] = __float_as_uint(sa[(m+g  )*GSTR + ko + t4 + 4]);
                ah[3] = __float_as_uint(sa[(m+g+8)*GSTR + ko + t4 + 4]);
                al[0] = __float_as_uint(sa[GTILE + (m+g  )*GSTR + ko + t4]);
                al[1] = __float_as_uint(sa[GTILE + (m+g+8)*GSTR + ko + t4]);
                al[2] = __float_as_uint(sa[GTILE + (m+g  )*GSTR + ko + t4 + 4]);
                al[3] = __float_as_uint(sa[GTILE + (m+g+8)*GSTR + ko + t4 + 4]);
                #pragma unroll
                for (int nt = 0; nt < 4; nt++) {
                    mma8(acc[mt][nt], ah, bh[nt]);
                    mma8(acc[mt][nt], al, bh[nt]);
                    mma8(acc[mt][nt], ah, bl[nt]);
                }
            }
        }

        if (pf) {
            float* st = sm + ((kt+1) & 1) * (4*GTILE);
            stash4(st +            crow*GSTR + ccol,     st +   GTILE + crow*GSTR + ccol,     ra0);
            stash4(st +            crow*GSTR + ccol + 4, st +   GTILE + crow*GSTR + ccol + 4, ra1);
            stash4(st + 2*GTILE +  crow*GSTR + ccol,     st + 3*GTILE + crow*GSTR + ccol,     rb0);
            stash4(st + 2*GTILE +  crow*GSTR + ccol + 4, st + 3*GTILE + crow*GSTR + ccol + 4, rb1);
        }
        __syncthreads();
    }

    #pragma unroll
    for (int mt = 0; mt < 4; mt++) {
        const int row = m0 + warpM + mt*16 + g;
        #pragma unroll
        for (int nt = 0; nt < 4; nt++) {
            const int col = n0 + warpN + nt*8 + 2*t4;
            const float bv0 = bias[col], bv1 = bias[col+1];
            float2 v0 = {acc[mt][nt][0] + bv0, acc[mt][nt][1] + bv1};
            float2 v1 = {acc[mt][nt][2] + bv0, acc[mt][nt][3] + bv1};
            *(float2*)(C + (size_t)row     * N + col) = v0;
            *(float2*)(C + (size_t)(row+8) * N + col) = v1;
        }
    }
}

// ---------------------------------------------------------------------------
// TF32 tensor-core flash attention, causal. Block = 64 query rows of one
// (b,h); 4 warps x 16 rows. Bc = 64 keys/iter. Online softmax on fragments.
// ---------------------------------------------------------------------------
#define ASTR 76
#define ATILE (64*ASTR)

__global__ __launch_bounds__(128) void attn_mma(
    const float* __restrict__ Qp, const float* __restrict__ Kp,
    const float* __restrict__ Vp, float* __restrict__ Op)
{
    extern __shared__ float sm[];
    float* Qs = sm;
    float* Ks = sm +     ATILE;
    float* Vs = sm + 2 * ATILE;
    float* Ss = sm + 3 * ATILE;

    const int tid  = threadIdx.x;
    const int warp = tid >> 5, lane = tid & 31;
    const int g = lane >> 2, t4 = lane & 3;
    const int qt = blockIdx.x, h = blockIdx.y, b = blockIdx.z;
    const int w16 = warp * 16;

    // load Q tile, pre-scaled and pre-rounded to tf32
    {
        const int row = tid >> 1, cb = (tid & 1) * 32;
        const float* src = Qp + (size_t)(b*SEQ + qt*64 + row)*DM + h*DKH + cb;
        float* dst = Qs + row*ASTR + cb;
        #pragma unroll
        for (int i = 0; i < 8; i++) {
            float4 v = *(const float4*)(src + i*4);
            float4 o;
            o.x = __uint_as_float(f2tf(v.x * 0.125f));
            o.y = __uint_as_float(f2tf(v.y * 0.125f));
            o.z = __uint_as_float(f2tf(v.z * 0.125f));
            o.w = __uint_as_float(f2tf(v.w * 0.125f));
            *(float4*)(dst + i*4) = o;
        }
    }

    float o[8][4];
    #pragma unroll
    for (int nn=0;nn<8;nn++)
        #pragma unroll
        for (int c=0;c<4;c++) o[nn][c] = 0.f;
    float mrow0 = -1e30f, mrow1 = -1e30f, lrow0 = 0.f, lrow1 = 0.f;

    const unsigned* Qu = (const unsigned*)Qs;
    const unsigned* Ku = (const unsigned*)Ks;
    const unsigned* Vu = (const unsigned*)Vs;
    unsigned*       Su = (unsigned*)Ss;

    for (int kt = 0; kt <= qt; kt++) {
        // load K/V tile (tf32-rounded at store)
        {
            const int row = tid >> 1, cb = (tid & 1) * 32;
            const size_t so = (size_t)(b*SEQ + kt*64 + row)*DM + h*DKH + cb;
            #pragma unroll
            for (int i = 0; i < 8; i++) {
                float4 kv = *(const float4*)(Kp + so + i*4);
                float4 vv = *(const float4*)(Vp + so + i*4);
                float4 ko, vo;
                ko.x=__uint_as_float(f2tf(kv.x)); ko.y=__uint_as_float(f2tf(kv.y));
                ko.z=__uint_as_float(f2tf(kv.z)); ko.w=__uint_as_float(f2tf(kv.w));
                vo.x=__uint_as_float(f2tf(vv.x)); vo.y=__uint_as_float(f2tf(vv.y));
                vo.z=__uint_as_float(f2tf(vv.z)); vo.w=__uint_as_float(f2tf(vv.w));
                *(float4*)(Ks + row*ASTR + cb + i*4) = ko;
                *(float4*)(Vs + row*ASTR + cb + i*4) = vo;
            }
        }
        __syncthreads();

        // S = Q @ K^T  (warp strip: rows w16..w16+15, cols 0..63)
        float s[8][4];
        #pragma unroll
        for (int nn=0;nn<8;nn++)
            #pragma unroll
            for (int c=0;c<4;c++) s[nn][c] = 0.f;

        #pragma unroll
        for (int kk = 0; kk < 8; kk++) {
            const int ko = kk * 8;
            unsigned a[4];
            a[0] = Qu[(w16+g  )*ASTR + ko + t4];
            a[1] = Qu[(w16+g+8)*ASTR + ko + t4];
            a[2] = Qu[(w16+g  )*ASTR + ko + t4 + 4];
            a[3] = Qu[(w16+g+8)*ASTR + ko + t4 + 4];
            #pragma unroll
            for (int nn = 0; nn < 8; nn++) {
                unsigned bb[2];
                bb[0] = Ku[(nn*8+g)*ASTR + ko + t4];
                bb[1] = Ku[(nn*8+g)*ASTR + ko + t4 + 4];
                mma8(s[nn], a, bb);
            }
        }

        // causal mask on the diagonal tile
        if (kt == qt) {
            #pragma unroll
            for (int nn = 0; nn < 8; nn++) {
                const int col = nn*8 + 2*t4;
                if (col     > w16+g  ) s[nn][0] = -1e30f;
                if (col + 1 > w16+g  ) s[nn][1] = -1e30f;
                if (col     > w16+g+8) s[nn][2] = -1e30f;
                if (col + 1 > w16+g+8) s[nn][3] = -1e30f;
            }
        }

        // online softmax
        float mx0 = -1e30f, mx1 = -1e30f;
        #pragma unroll
        for (int nn = 0; nn < 8; nn++) {
            mx0 = fmaxf(mx0, fmaxf(s[nn][0], s[nn][1]));
            mx1 = fmaxf(mx1, fmaxf(s[nn][2], s[nn][3]));
        }
        mx0 = fmaxf(mx0, __shfl_xor_sync(0xffffffffu, mx0, 1));
        mx0 = fmaxf(mx0, __shfl_xor_sync(0xffffffffu, mx0, 2));
        mx1 = fmaxf(mx1, __shfl_xor_sync(0xffffffffu, mx1, 1));
        mx1 = fmaxf(mx1, __shfl_xor_sync(0xffffffffu, mx1, 2));

        const float mn0 = fmaxf(mrow0, mx0), mn1 = fmaxf(mrow1, mx1);
        const float cr0 = __expf(mrow0 - mn0), cr1 = __expf(mrow1 - mn1);
        lrow0 *= cr0; lrow1 *= cr1;
        #pragma unroll
        for (int nn = 0; nn < 8; nn++) {
            o[nn][0] *= cr0; o[nn][1] *= cr0;
            o[nn][2] *= cr1; o[nn][3] *= cr1;
        }
        mrow0 = mn0; mrow1 = mn1;

        #pragma unroll
        for (int nn = 0; nn < 8; nn++) {
            const float p0 = __expf(s[nn][0] - mn0);
            const float p1 = __expf(s[nn][1] - mn0);
            const float p2 = __expf(s[nn][2] - mn1);
            const float p3 = __expf(s[nn][3] - mn1);
            lrow0 += p0 + p1;
            lrow1 += p2 + p3;
            const int col = nn*8 + 2*t4;
            Su[(w16+g  )*ASTR + col    ] = f2tf(p0);
            Su[(w16+g  )*ASTR + col + 1] = f2tf(p1);
            Su[(w16+g+8)*ASTR + col    ] = f2tf(p2);
            Su[(w16+g+8)*ASTR + col + 1] = f2tf(p3);
        }
        __syncwarp();

        // O += P @ V   (warp-local rows of P, shared V)
        #pragma unroll
        for (int kk = 0; kk < 8; kk++) {
            const int ko = kk * 8;
            unsigned a[4];
            a[0] = Su[(w16+g  )*ASTR + ko + t4];
            a[1] = Su[(w16+g+8)*ASTR + ko + t4];
            a[2] = Su[(w16+g  )*ASTR + ko + t4 + 4];
            a[3] = Su[(w16+g+8)*ASTR + ko + t4 + 4];
            #pragma unroll
            for (int nn = 0; nn < 8; nn++) {
                unsigned bb[2];
                bb[0] = Vu[(ko + t4    )*ASTR + nn*8 + g];
                bb[1] = Vu[(ko + t4 + 4)*ASTR + nn*8 + g];
                mma8(o[nn], a, bb);
            }
        }
        __syncthreads();   // before next tile overwrites Ks/Vs
    }

    // final normalize + store
    lrow0 += __shfl_xor_sync(0xffffffffu, lrow0, 1);
    lrow0 += __shfl_xor_sync(0xffffffffu, lrow0, 2);
    lrow1 += __shfl_xor_sync(0xffffffffu, lrow1, 1);
    lrow1 += __shfl_xor_sync(0xffffffffu, lrow1, 2);
    const float inv0 = 1.f / lrow0, inv1 = 1.f / lrow1;

    const int rowg = b*SEQ + qt*64 + w16 + g;
    float* base0 = g_Op + (size_t)rowg     * DM + h*DKH;
    float* base1 = g_Op + (size_t)(rowg+8) * DM + h*DKH;
    #pragma unroll
    for (int nn = 0; nn < 8; nn++) {
        const int col = nn*8 + 2*t4;
        float2 v0 = {o[nn][0]*inv0, o[nn][1]*inv0};
        float2 v1 = {o[nn][2]*inv1, o[nn][3]*inv1};
        *(float2*)(base0 + col) = v0;
        *(float2*)(base1 + col) = v1;
    }
}

extern "C" void kernel_launch(void* const* d_in, const int* in_sizes, int n_in,
                              void* d_out, int out_size)
{
    const float* q   = (const float*)d_in[0];
    const float* k   = (const float*)d_in[1];
    const float* v   = (const float*)d_in[2];
    // d_in[3]: causal mask (tril) — computed analytically in-kernel.
    const float* w_q = (const float*)d_in[4];
    const float* b_q = (const float*)d_in[5];
    const float* w_k = (const float*)d_in[6];
    const float* b_k = (const float*)d_in[7];
    const float* w_v = (const float*)d_in[8];
    const float* b_v = (const float*)d_in[9];
    const float* w_o = (const float*)d_in[10];
    const float* b_o = (const float*)d_in[11];
    float* out = (float*)d_out;

    float *Qp, *Kp, *Vp, *Op;
    cudaGetSymbolAddress((void**)&Qp, g_Qp);
    cudaGetSymbolAddress((void**)&Kp, g_Kp);
    cudaGetSymbolAddress((void**)&Vp, g_Vp);
    cudaGetSymbolAddress((void**)&Op, g_Op);

    const int gemm_smem = 2 * 4 * GTILE * (int)sizeof(float);   // 81920
    const int attn_smem = 4 * ATILE * (int)sizeof(float);       // 77824
    cudaFuncSetAttribute(gemm3_bias, cudaFuncAttributeMaxDynamicSharedMemorySize, gemm_smem);
    cudaFuncSetAttribute(attn_mma,  cudaFuncAttributeMaxDynamicSharedMemorySize, attn_smem);

    dim3 ggrid(DM / 128, MROWS / 128);   // (8, 64)
    gemm3_bias<<<ggrid, 256, gemm_smem>>>(q, w_q, b_q, Qp, MROWS, DM, DM);
    gemm3_bias<<<ggrid, 256, gemm_smem>>>(k, w_k, b_k, Kp, MROWS, DM, DM);
    gemm3_bias<<<ggrid, 256, gemm_smem>>>(v, w_v, b_v, Vp, MROWS, DM, DM);

    dim3 agrid(SEQ / 64, NH, BATCH);     // (32, 16, 4)
    attn_mma<<<agrid, 128, attn_smem>>>(Qp, Kp, Vp, Op);

    gemm3_bias<<<ggrid, 256, gemm_smem>>>(Op, w_o, b_o, out, MROWS, DM, DM);
}

// round 5
// speedup vs baseline: 4.3705x; 1.6460x over previous
#include <cuda_runtime.h>
#include <cuda_bf16.h>
#include <math.h>

#define BATCH 4
#define SEQ   2048
#define DM    1024
#define NH    16
#define DKH   64
#define MROWS (BATCH*SEQ)   // 8192

// Scratch (device globals: allocation-free per harness rules)
__device__ float g_Qp[MROWS*DM];
__device__ float g_Kp[MROWS*DM];
__device__ float g_Vp[MROWS*DM];
__device__ float g_Op[MROWS*DM];

// ---------------------------------------------------------------------------
// helpers
// ---------------------------------------------------------------------------
__device__ __forceinline__ unsigned pack2(float e0, float e1){
    // result: lo half = bf16(e0), hi half = bf16(e1)
    unsigned r; asm("cvt.rn.bf16x2.f32 %0, %1, %2;" : "=r"(r) : "f"(e1), "f"(e0));
    return r;
}
// split 4 floats into bf16 hi pair-regs and lo pair-regs
__device__ __forceinline__ void split4(float4 v, unsigned &h0, unsigned &h1,
                                       unsigned &l0, unsigned &l1){
    h0 = pack2(v.x, v.y);
    h1 = pack2(v.z, v.w);
    float hx = __uint_as_float(h0 << 16);
    float hy = __uint_as_float(h0 & 0xffff0000u);
    float hz = __uint_as_float(h1 << 16);
    float hw = __uint_as_float(h1 & 0xffff0000u);
    l0 = pack2(v.x - hx, v.y - hy);
    l1 = pack2(v.z - hz, v.w - hw);
}
__device__ __forceinline__ void mma16(float c[4], const unsigned a[4],
                                      unsigned b0, unsigned b1){
    asm volatile("mma.sync.aligned.m16n8k16.row.col.f32.bf16.bf16.f32 "
        "{%0,%1,%2,%3},{%4,%5,%6,%7},{%8,%9},{%0,%1,%2,%3};\n"
        : "+f"(c[0]),"+f"(c[1]),"+f"(c[2]),"+f"(c[3])
        : "r"(a[0]),"r"(a[1]),"r"(a[2]),"r"(a[3]),"r"(b0),"r"(b1));
}
__device__ __forceinline__ void ldsm4(unsigned r[4], const void* p){
    unsigned addr = (unsigned)__cvta_generic_to_shared(p);
    asm volatile("ldmatrix.sync.aligned.m8n8.x4.shared.b16 {%0,%1,%2,%3},[%4];"
        : "=r"(r[0]),"=r"(r[1]),"=r"(r[2]),"=r"(r[3]) : "r"(addr));
}
__device__ __forceinline__ void ldsm4t(unsigned r[4], const void* p){
    unsigned addr = (unsigned)__cvta_generic_to_shared(p);
    asm volatile("ldmatrix.sync.aligned.m8n8.x4.trans.shared.b16 {%0,%1,%2,%3},[%4];"
        : "=r"(r[0]),"=r"(r[1]),"=r"(r[2]),"=r"(r[3]) : "r"(addr));
}

// ---------------------------------------------------------------------------
// 3xBF16 GEMM:  C[m,n] = sum_k A[m,k]*W[n,k] + bias[n]   (both K-major)
// 128x128x16 tiles, 256 threads, 8 warps (64x32 each), double-buffered smem,
// ldmatrix operand loads, hi/lo bf16 split (hh + lh + hl).
// ---------------------------------------------------------------------------
#define GS 24              // bf16 elems per smem row (48B: 16B-aligned, conflict-free)
#define GT (128*GS)        // elems per tile buffer
#define GSTAGE (4*GT)      // Ah|Al|Bh|Bl

__global__ __launch_bounds__(256, 2) void gemm3_bias(
    const float* __restrict__ A, const float* __restrict__ W,
    const float* __restrict__ bias, float* __restrict__ C,
    int M, int N, int K)
{
    extern __shared__ __nv_bfloat16 smb[];

    const int tid  = threadIdx.x;
    const int warp = tid >> 5, lane = tid & 31;
    const int g = lane >> 2, t4 = lane & 3;
    const int lr = lane & 7, grp = lane >> 3;
    const int warpM = (warp >> 2) * 64;
    const int warpN = (warp & 3) * 32;
    const int m0 = blockIdx.y * 128, n0 = blockIdx.x * 128;

    const int crow = tid >> 1;          // 0..127
    const int ccol = (tid & 1) * 8;     // 0 or 8

    const float* Aptr = A + (size_t)(m0 + crow) * K + ccol;
    const float* Wptr = W + (size_t)(n0 + crow) * K + ccol;

    float acc[4][4][4];
    #pragma unroll
    for (int i=0;i<4;i++)
        #pragma unroll
        for (int j=0;j<4;j++)
            #pragma unroll
            for (int c=0;c<4;c++) acc[i][j][c] = 0.f;

    const int KT = K >> 4;

    // ldmatrix source offsets (element units within a tile buffer)
    const int aoff = (lr + (grp & 1) * 8) * GS + (grp >> 1) * 8;   // A-operand (m16k16)
    const int boff = (lr + (grp >> 1) * 8) * GS + (grp & 1) * 8;   // B-operand (n16k16)
    const int stoff = crow * GS + ccol;                            // store offset

    // prologue: tile 0 -> stage 0
    float4 ra0 = *(const float4*)(Aptr);
    float4 ra1 = *(const float4*)(Aptr + 4);
    float4 rb0 = *(const float4*)(Wptr);
    float4 rb1 = *(const float4*)(Wptr + 4);
    {
        unsigned h0,h1,l0,l1, h2,h3,l2,l3;
        split4(ra0, h0,h1,l0,l1); split4(ra1, h2,h3,l2,l3);
        *(uint4*)(smb + stoff)      = make_uint4(h0,h1,h2,h3);
        *(uint4*)(smb + GT + stoff) = make_uint4(l0,l1,l2,l3);
        split4(rb0, h0,h1,l0,l1); split4(rb1, h2,h3,l2,l3);
        *(uint4*)(smb + 2*GT + stoff) = make_uint4(h0,h1,h2,h3);
        *(uint4*)(smb + 3*GT + stoff) = make_uint4(l0,l1,l2,l3);
    }
    __syncthreads();

    for (int kt = 0; kt < KT; kt++) {
        const __nv_bfloat16* Ah = smb + (kt & 1) * GSTAGE;
        const __nv_bfloat16* Al = Ah + GT;
        const __nv_bfloat16* Bh = Ah + 2*GT;
        const __nv_bfloat16* Bl = Ah + 3*GT;
        const bool pf = (kt + 1 < KT);
        if (pf) {
            const float* Ap = Aptr + (kt+1)*16;
            const float* Wp = Wptr + (kt+1)*16;
            ra0 = *(const float4*)(Ap);
            ra1 = *(const float4*)(Ap + 4);
            rb0 = *(const float4*)(Wp);
            rb1 = *(const float4*)(Wp + 4);
        }

        unsigned bh[2][4], bl[2][4];
        #pragma unroll
        for (int ng = 0; ng < 2; ng++) {
            const int off = (warpN + ng*16) * GS + boff;
            ldsm4(bh[ng], Bh + off);
            ldsm4(bl[ng], Bl + off);
        }
        #pragma unroll
        for (int mt = 0; mt < 4; mt++) {
            unsigned ah[4], al[4];
            const int off = (warpM + mt*16) * GS + aoff;
            ldsm4(ah, Ah + off);
            ldsm4(al, Al + off);
            #pragma unroll
            for (int ng = 0; ng < 2; ng++) {
                #pragma unroll
                for (int hf = 0; hf < 2; hf++) {
                    const int nt = ng*2 + hf;
                    const unsigned b0h = bh[ng][2*hf], b1h = bh[ng][2*hf+1];
                    mma16(acc[mt][nt], ah, b0h, b1h);
                    mma16(acc[mt][nt], al, b0h, b1h);
                    mma16(acc[mt][nt], ah, bl[ng][2*hf], bl[ng][2*hf+1]);
                }
            }
        }

        if (pf) {
            __nv_bfloat16* st = smb + ((kt+1) & 1) * GSTAGE;
            unsigned h0,h1,l0,l1, h2,h3,l2,l3;
            split4(ra0, h0,h1,l0,l1); split4(ra1, h2,h3,l2,l3);
            *(uint4*)(st + stoff)      = make_uint4(h0,h1,h2,h3);
            *(uint4*)(st + GT + stoff) = make_uint4(l0,l1,l2,l3);
            split4(rb0, h0,h1,l0,l1); split4(rb1, h2,h3,l2,l3);
            *(uint4*)(st + 2*GT + stoff) = make_uint4(h0,h1,h2,h3);
            *(uint4*)(st + 3*GT + stoff) = make_uint4(l0,l1,l2,l3);
        }
        __syncthreads();
    }

    #pragma unroll
    for (int mt = 0; mt < 4; mt++) {
        const int row = m0 + warpM + mt*16 + g;
        #pragma unroll
        for (int nt = 0; nt < 4; nt++) {
            const int col = n0 + warpN + nt*8 + 2*t4;
            const float bv0 = bias[col], bv1 = bias[col+1];
            float2 v0 = {acc[mt][nt][0] + bv0, acc[mt][nt][1] + bv1};
            float2 v1 = {acc[mt][nt][2] + bv0, acc[mt][nt][3] + bv1};
            *(float2*)(C + (size_t)row     * N + col) = v0;
            *(float2*)(C + (size_t)(row+8) * N + col) = v1;
        }
    }
}

// ---------------------------------------------------------------------------
// BF16 tensor-core flash attention, causal. Block = 64 query rows of one
// (b,h); 4 warps x 16 rows; 64 keys/iter. Q/K hi/lo 3xbf16 for S; P kept in
// registers (C-frag -> A-frag passthrough), split hi/lo; V hi/lo in smem via
// ldmatrix.trans.  O = Ph*Vh + Ph*Vl + Pl*Vh.
// ---------------------------------------------------------------------------
#define AS 72              // bf16 elems per smem row (144B: aligned, conflict-free)
#define ATE (64*AS)

__global__ __launch_bounds__(128) void attn_mma(
    const float* __restrict__ Qp, const float* __restrict__ Kp,
    const float* __restrict__ Vp, float* __restrict__ Op)
{
    extern __shared__ __nv_bfloat16 sb[];
    __nv_bfloat16* Qh = sb;
    __nv_bfloat16* Ql = sb +     ATE;
    __nv_bfloat16* Kh = sb + 2 * ATE;
    __nv_bfloat16* Kl = sb + 3 * ATE;
    __nv_bfloat16* Vh = sb + 4 * ATE;
    __nv_bfloat16* Vl = sb + 5 * ATE;

    const int tid  = threadIdx.x;
    const int warp = tid >> 5, lane = tid & 31;
    const int g = lane >> 2, t4 = lane & 3;
    const int lr = lane & 7, grp = lane >> 3;
    const int qt = (int)gridDim.x - 1 - (int)blockIdx.x;   // long blocks first
    const int h = blockIdx.y, b = blockIdx.z;
    const int w16 = warp * 16;

    // ---- load Q tile (scaled), split hi/lo ----
    {
        const int row = tid >> 1, cb = (tid & 1) * 32;
        const float* src = Qp + (size_t)(b*SEQ + qt*64 + row)*DM + h*DKH + cb;
        #pragma unroll
        for (int i = 0; i < 8; i++) {
            float4 v = *(const float4*)(src + i*4);
            v.x *= 0.125f; v.y *= 0.125f; v.z *= 0.125f; v.w *= 0.125f;
            unsigned h0,h1,l0,l1;
            split4(v, h0,h1,l0,l1);
            *(uint2*)(Qh + row*AS + cb + i*4) = make_uint2(h0,h1);
            *(uint2*)(Ql + row*AS + cb + i*4) = make_uint2(l0,l1);
        }
    }
    __syncthreads();

    // Q fragments, persistent (A-operand layout)
    unsigned qh[4][4], ql[4][4];
    #pragma unroll
    for (int kc = 0; kc < 4; kc++) {
        const int off = (w16 + lr + (grp & 1)*8)*AS + kc*16 + (grp >> 1)*8;
        ldsm4(qh[kc], Qh + off);
        ldsm4(ql[kc], Ql + off);
    }

    float o[8][4];
    #pragma unroll
    for (int nn=0;nn<8;nn++)
        #pragma unroll
        for (int c=0;c<4;c++) o[nn][c] = 0.f;
    float mrow0 = -1e30f, mrow1 = -1e30f, lrow0 = 0.f, lrow1 = 0.f;

    for (int kt = 0; kt <= qt; kt++) {
        // ---- load K/V tile, split hi/lo ----
        {
            const int row = tid >> 1, cb = (tid & 1) * 32;
            const size_t so = (size_t)(b*SEQ + kt*64 + row)*DM + h*DKH + cb;
            #pragma unroll
            for (int i = 0; i < 8; i++) {
                float4 kv = *(const float4*)(Kp + so + i*4);
                float4 vv = *(const float4*)(Vp + so + i*4);
                unsigned h0,h1,l0,l1;
                split4(kv, h0,h1,l0,l1);
                *(uint2*)(Kh + row*AS + cb + i*4) = make_uint2(h0,h1);
                *(uint2*)(Kl + row*AS + cb + i*4) = make_uint2(l0,l1);
                split4(vv, h0,h1,l0,l1);
                *(uint2*)(Vh + row*AS + cb + i*4) = make_uint2(h0,h1);
                *(uint2*)(Vl + row*AS + cb + i*4) = make_uint2(l0,l1);
            }
        }
        __syncthreads();

        // ---- S = Q K^T (3xbf16) ----
        float s[8][4];
        #pragma unroll
        for (int nn=0;nn<8;nn++)
            #pragma unroll
            for (int c=0;c<4;c++) s[nn][c] = 0.f;

        #pragma unroll
        for (int kc = 0; kc < 4; kc++) {
            #pragma unroll
            for (int ng = 0; ng < 4; ng++) {
                unsigned kh4[4], kl4[4];
                const int off = (ng*16 + lr + (grp >> 1)*8)*AS + kc*16 + (grp & 1)*8;
                ldsm4(kh4, Kh + off);
                ldsm4(kl4, Kl + off);
                #pragma unroll
                for (int hf = 0; hf < 2; hf++) {
                    const int nn = ng*2 + hf;
                    const unsigned b0 = kh4[2*hf], b1 = kh4[2*hf+1];
                    mma16(s[nn], qh[kc], b0, b1);
                    mma16(s[nn], ql[kc], b0, b1);
                    mma16(s[nn], qh[kc], kl4[2*hf], kl4[2*hf+1]);
                }
            }
        }

        // ---- causal mask on diagonal tile ----
        if (kt == qt) {
            #pragma unroll
            for (int nn = 0; nn < 8; nn++) {
                const int col = nn*8 + 2*t4;
                if (col     > w16+g  ) s[nn][0] = -1e30f;
                if (col + 1 > w16+g  ) s[nn][1] = -1e30f;
                if (col     > w16+g+8) s[nn][2] = -1e30f;
                if (col + 1 > w16+g+8) s[nn][3] = -1e30f;
            }
        }

        // ---- online softmax (in registers; s overwritten with p) ----
        float mx0 = -1e30f, mx1 = -1e30f;
        #pragma unroll
        for (int nn = 0; nn < 8; nn++) {
            mx0 = fmaxf(mx0, fmaxf(s[nn][0], s[nn][1]));
            mx1 = fmaxf(mx1, fmaxf(s[nn][2], s[nn][3]));
        }
        mx0 = fmaxf(mx0, __shfl_xor_sync(0xffffffffu, mx0, 1));
        mx0 = fmaxf(mx0, __shfl_xor_sync(0xffffffffu, mx0, 2));
        mx1 = fmaxf(mx1, __shfl_xor_sync(0xffffffffu, mx1, 1));
        mx1 = fmaxf(mx1, __shfl_xor_sync(0xffffffffu, mx1, 2));

        const float mn0 = fmaxf(mrow0, mx0), mn1 = fmaxf(mrow1, mx1);
        const float cr0 = __expf(mrow0 - mn0), cr1 = __expf(mrow1 - mn1);
        lrow0 *= cr0; lrow1 *= cr1;
        #pragma unroll
        for (int nn = 0; nn < 8; nn++) {
            o[nn][0] *= cr0; o[nn][1] *= cr0;
            o[nn][2] *= cr1; o[nn][3] *= cr1;
        }
        mrow0 = mn0; mrow1 = mn1;

        #pragma unroll
        for (int nn = 0; nn < 8; nn++) {
            const float p0 = __expf(s[nn][0] - mn0);
            const float p1 = __expf(s[nn][1] - mn0);
            const float p2 = __expf(s[nn][2] - mn1);
            const float p3 = __expf(s[nn][3] - mn1);
            lrow0 += p0 + p1;
            lrow1 += p2 + p3;
            s[nn][0] = p0; s[nn][1] = p1; s[nn][2] = p2; s[nn][3] = p3;
        }

        // ---- O += P V : P from registers (hi/lo), V via ldmatrix.trans ----
        #pragma unroll
        for (int kc = 0; kc < 4; kc++) {
            const float* sA = s[2*kc];
            const float* sB = s[2*kc+1];
            unsigned ph[4], pl[4];
            ph[0] = pack2(sA[0], sA[1]);
            ph[1] = pack2(sA[2], sA[3]);
            ph[2] = pack2(sB[0], sB[1]);
            ph[3] = pack2(sB[2], sB[3]);
            #pragma unroll
            for (int r = 0; r < 4; r++) {
                const float* sp = (r < 2) ? sA : sB;
                const int e = (r & 1) * 2;
                const float h0f = __uint_as_float(ph[r] << 16);
                const float h1f = __uint_as_float(ph[r] & 0xffff0000u);
                pl[r] = pack2(sp[e] - h0f, sp[e+1] - h1f);
            }
            #pragma unroll
            for (int dt = 0; dt < 4; dt++) {
                unsigned vh4[4], vl4[4];
                const int off = (kc*16 + lr + (grp & 1)*8)*AS + dt*16 + (grp >> 1)*8;
                ldsm4t(vh4, Vh + off);
                ldsm4t(vl4, Vl + off);
                #pragma unroll
                for (int hf = 0; hf < 2; hf++) {
                    const int nd = dt*2 + hf;
                    const unsigned b0 = vh4[2*hf], b1 = vh4[2*hf+1];
                    mma16(o[nd], ph, b0, b1);
                    mma16(o[nd], ph, vl4[2*hf], vl4[2*hf+1]);
                    mma16(o[nd], pl, b0, b1);
                }
            }
        }
        __syncthreads();   // before next tile overwrites Kh/Kl/Vh/Vl
    }

    // ---- final normalize + store ----
    lrow0 += __shfl_xor_sync(0xffffffffu, lrow0, 1);
    lrow0 += __shfl_xor_sync(0xffffffffu, lrow0, 2);
    lrow1 += __shfl_xor_sync(0xffffffffu, lrow1, 1);
    lrow1 += __shfl_xor_sync(0xffffffffu, lrow1, 2);
    const float inv0 = 1.f / lrow0, inv1 = 1.f / lrow1;

    const int rowg = b*SEQ + qt*64 + w16 + g;
    float* base0 = Op + (size_t)rowg     * DM + h*DKH;
    float* base1 = Op + (size_t)(rowg+8) * DM + h*DKH;
    #pragma unroll
    for (int nn = 0; nn < 8; nn++) {
        const int col = nn*8 + 2*t4;
        float2 v0 = {o[nn][0]*inv0, o[nn][1]*inv0};
        float2 v1 = {o[nn][2]*inv1, o[nn][3]*inv1};
        *(float2*)(base0 + col) = v0;
        *(float2*)(base1 + col) = v1;
    }
}

extern "C" void kernel_launch(void* const* d_in, const int* in_sizes, int n_in,
                              void* d_out, int out_size)
{
    const float* q   = (const float*)d_in[0];
    const float* k   = (const float*)d_in[1];
    const float* v   = (const float*)d_in[2];
    // d_in[3]: causal mask (tril) — computed analytically in-kernel.
    const float* w_q = (const float*)d_in[4];
    const float* b_q = (const float*)d_in[5];
    const float* w_k = (const float*)d_in[6];
    const float* b_k = (const float*)d_in[7];
    const float* w_v = (const float*)d_in[8];
    const float* b_v = (const float*)d_in[9];
    const float* w_o = (const float*)d_in[10];
    const float* b_o = (const float*)d_in[11];
    float* out = (float*)d_out;

    float *Qp, *Kp, *Vp, *Op;
    cudaGetSymbolAddress((void**)&Qp, g_Qp);
    cudaGetSymbolAddress((void**)&Kp, g_Kp);
    cudaGetSymbolAddress((void**)&Vp, g_Vp);
    cudaGetSymbolAddress((void**)&Op, g_Op);

    const int gemm_smem = 2 * GSTAGE * (int)sizeof(__nv_bfloat16);  // 49152
    const int attn_smem = 6 * ATE * (int)sizeof(__nv_bfloat16);     // 55296
    cudaFuncSetAttribute(gemm3_bias, cudaFuncAttributeMaxDynamicSharedMemorySize, gemm_smem);
    cudaFuncSetAttribute(attn_mma,  cudaFuncAttributeMaxDynamicSharedMemorySize, attn_smem);

    dim3 ggrid(DM / 128, MROWS / 128);   // (8, 64)
    gemm3_bias<<<ggrid, 256, gemm_smem>>>(q, w_q, b_q, Qp, MROWS, DM, DM);
    gemm3_bias<<<ggrid, 256, gemm_smem>>>(k, w_k, b_k, Kp, MROWS, DM, DM);
    gemm3_bias<<<ggrid, 256, gemm_smem>>>(v, w_v, b_v, Vp, MROWS, DM, DM);

    dim3 agrid(SEQ / 64, NH, BATCH);     // (32, 16, 4)
    attn_mma<<<agrid, 128, attn_smem>>>(Qp, Kp, Vp, Op);

    gemm3_bias<<<ggrid, 256, gemm_smem>>>(Op, w_o, b_o, out, MROWS, DM, DM);
}

// round 7
// speedup vs baseline: 5.0681x; 1.1596x over previous
#include <cuda_runtime.h>
#include <cuda_bf16.h>

#define BATCH 4
#define SEQ   2048
#define DM    1024
#define NH    16
#define DKH   64
#define MROWS (BATCH*SEQ)      // 8192
#define NELEM (MROWS*DM)       // 8388608
#define WELEM (DM*DM)          // 1048576

// ---------------------------------------------------------------------------
// Scratch planes (device globals: allocation-free per harness rules)
// ---------------------------------------------------------------------------
__device__ __nv_bfloat16 g_aqh[NELEM], g_aql[NELEM];   // split q input
__device__ __nv_bfloat16 g_akh[NELEM], g_akl[NELEM];   // split k input
__device__ __nv_bfloat16 g_avh[NELEM], g_avl[NELEM];   // split v input
__device__ __nv_bfloat16 g_wqh[WELEM], g_wql[WELEM];
__device__ __nv_bfloat16 g_wkh[WELEM], g_wkl[WELEM];
__device__ __nv_bfloat16 g_wvh[WELEM], g_wvl[WELEM];
__device__ __nv_bfloat16 g_woh[WELEM], g_wol[WELEM];
__device__ __nv_bfloat16 g_Qh[NELEM],  g_Ql[NELEM];    // projected Q planes
__device__ __nv_bfloat16 g_Kh[NELEM],  g_Kl[NELEM];
__device__ __nv_bfloat16 g_Vh[NELEM],  g_Vl[NELEM];
__device__ __nv_bfloat16 g_Oh[NELEM],  g_Ol[NELEM];    // attention out planes

// ---------------------------------------------------------------------------
// helpers
// ---------------------------------------------------------------------------
__device__ __forceinline__ unsigned pack2(float e0, float e1){
    unsigned r; asm("cvt.rn.bf16x2.f32 %0, %1, %2;" : "=r"(r) : "f"(e1), "f"(e0));
    return r;   // lo half = bf16(e0), hi half = bf16(e1)
}
__device__ __forceinline__ void split4(float4 v, unsigned &h0, unsigned &h1,
                                       unsigned &l0, unsigned &l1){
    h0 = pack2(v.x, v.y);
    h1 = pack2(v.z, v.w);
    float hx = __uint_as_float(h0 << 16);
    float hy = __uint_as_float(h0 & 0xffff0000u);
    float hz = __uint_as_float(h1 << 16);
    float hw = __uint_as_float(h1 & 0xffff0000u);
    l0 = pack2(v.x - hx, v.y - hy);
    l1 = pack2(v.z - hz, v.w - hw);
}
__device__ __forceinline__ void mma16(float c[4], const unsigned a[4],
                                      unsigned b0, unsigned b1){
    asm volatile("mma.sync.aligned.m16n8k16.row.col.f32.bf16.bf16.f32 "
        "{%0,%1,%2,%3},{%4,%5,%6,%7},{%8,%9},{%0,%1,%2,%3};\n"
        : "+f"(c[0]),"+f"(c[1]),"+f"(c[2]),"+f"(c[3])
        : "r"(a[0]),"r"(a[1]),"r"(a[2]),"r"(a[3]),"r"(b0),"r"(b1));
}
__device__ __forceinline__ void ldsm4(unsigned r[4], const void* p){
    unsigned addr = (unsigned)__cvta_generic_to_shared(p);
    asm volatile("ldmatrix.sync.aligned.m8n8.x4.shared.b16 {%0,%1,%2,%3},[%4];"
        : "=r"(r[0]),"=r"(r[1]),"=r"(r[2]),"=r"(r[3]) : "r"(addr));
}
__device__ __forceinline__ void ldsm4t(unsigned r[4], const void* p){
    unsigned addr = (unsigned)__cvta_generic_to_shared(p);
    asm volatile("ldmatrix.sync.aligned.m8n8.x4.trans.shared.b16 {%0,%1,%2,%3},[%4];"
        : "=r"(r[0]),"=r"(r[1]),"=r"(r[2]),"=r"(r[3]) : "r"(addr));
}
__device__ __forceinline__ void cp16(const void* smem_dst, const void* gmem_src){
    unsigned d = (unsigned)__cvta_generic_to_shared(smem_dst);
    asm volatile("cp.async.cg.shared.global [%0],[%1],16;" :: "r"(d), "l"(gmem_src));
}
__device__ __forceinline__ void cpcommit(){ asm volatile("cp.async.commit_group;"); }
template<int N> __device__ __forceinline__ void cpwait(){
    asm volatile("cp.async.wait_group %0;" :: "n"(N));
}

// ---------------------------------------------------------------------------
// split kernel: fp32 -> bf16 hi/lo planes
// ---------------------------------------------------------------------------
__global__ __launch_bounds__(256) void split_planes(
    const float4* __restrict__ x, uint2* __restrict__ hi, uint2* __restrict__ lo, int n4)
{
    int i = blockIdx.x * blockDim.x + threadIdx.x;
    if (i >= n4) return;
    float4 v = x[i];
    unsigned h0,h1,l0,l1;
    split4(v, h0,h1,l0,l1);
    hi[i] = make_uint2(h0,h1);
    lo[i] = make_uint2(l0,l1);
}

// ---------------------------------------------------------------------------
// 3xBF16 GEMM on pre-split operands. C[m,n] = sum_k A[m,k]*W[n,k] + bias[n].
// 128x128x32 tiles, 256 thr, 8 warps (64x32), cp.async 2-stage pipeline.
// SPLIT_OUT: write bf16 hi/lo planes instead of fp32.
// ---------------------------------------------------------------------------
#define GS2  40                 // bf16 elems per smem row (80B)
#define GPL  (128*GS2)          // elems per plane (5120)
#define GSTG (4*GPL)            // stage: Ah|Al|Bh|Bl (20480)

template<bool SPLIT_OUT>
__global__ __launch_bounds__(256, 2) void gemm3s(
    const __nv_bfloat16* __restrict__ Ah, const __nv_bfloat16* __restrict__ Al,
    const __nv_bfloat16* __restrict__ Bh, const __nv_bfloat16* __restrict__ Bl,
    const float* __restrict__ bias,
    float* __restrict__ C,
    __nv_bfloat16* __restrict__ Ch, __nv_bfloat16* __restrict__ Cl,
    int M, int N, int K)
{
    extern __shared__ __nv_bfloat16 smb[];
    const int tid  = threadIdx.x;
    const int warp = tid >> 5, lane = tid & 31;
    const int g = lane >> 2, t4 = lane & 3;
    const int lr = lane & 7, grp = lane >> 3;
    const int warpM = (warp >> 2) * 64;
    const int warpN = (warp & 3) * 32;
    const int m0 = blockIdx.y * 128, n0 = blockIdx.x * 128;

    float acc[4][4][4];
    #pragma unroll
    for (int i=0;i<4;i++)
        #pragma unroll
        for (int j=0;j<4;j++)
            #pragma unroll
            for (int c=0;c<4;c++) acc[i][j][c] = 0.f;

    auto issue = [&](int kt){
        const int st = (kt & 1) * GSTG;
        #pragma unroll
        for (int pl = 0; pl < 4; pl++){
            const __nv_bfloat16* base = (pl==0)?Ah:(pl==1)?Al:(pl==2)?Bh:Bl;
            const int rb = (pl < 2) ? m0 : n0;
            #pragma unroll
            for (int j = 0; j < 2; j++){
                const int cc = j*256 + tid;
                const int r = cc >> 2, col = (cc & 3) * 8;
                const __nv_bfloat16* src = base + (size_t)(rb + r)*K + kt*32 + col;
                cp16(smb + st + pl*GPL + r*GS2 + col, src);
            }
        }
        cpcommit();
    };

    const int KT = K >> 5;
    issue(0);

    for (int kt = 0; kt < KT; kt++){
        if (kt + 1 < KT){ issue(kt+1); cpwait<1>(); } else cpwait<0>();
        __syncthreads();

        const __nv_bfloat16* S   = smb + (kt & 1) * GSTG;
        const __nv_bfloat16* SAh = S;
        const __nv_bfloat16* SAl = S +     GPL;
        const __nv_bfloat16* SBh = S + 2 * GPL;
        const __nv_bfloat16* SBl = S + 3 * GPL;

        #pragma unroll
        for (int kc = 0; kc < 2; kc++){
            unsigned bh[2][4], bl[2][4];
            #pragma unroll
            for (int ng = 0; ng < 2; ng++){
                const int off = (warpN + ng*16 + lr + (grp>>1)*8)*GS2 + kc*16 + (grp&1)*8;
                ldsm4(bh[ng], SBh + off);
                ldsm4(bl[ng], SBl + off);
            }
            #pragma unroll
            for (int mt = 0; mt < 4; mt++){
                const int off = (warpM + mt*16 + lr + (grp&1)*8)*GS2 + kc*16 + (grp>>1)*8;
                unsigned ah[4], al[4];
                ldsm4(ah, SAh + off);
                ldsm4(al, SAl + off);
                #pragma unroll
                for (int ng = 0; ng < 2; ng++)
                    #pragma unroll
                    for (int hf = 0; hf < 2; hf++){
                        const int nt = ng*2 + hf;
                        const unsigned b0 = bh[ng][2*hf], b1 = bh[ng][2*hf+1];
                        mma16(acc[mt][nt], ah, b0, b1);
                        mma16(acc[mt][nt], al, b0, b1);
                        mma16(acc[mt][nt], ah, bl[ng][2*hf], bl[ng][2*hf+1]);
                    }
            }
        }
        __syncthreads();
    }

    #pragma unroll
    for (int mt = 0; mt < 4; mt++){
        const int row = m0 + warpM + mt*16 + g;
        #pragma unroll
        for (int nt = 0; nt < 4; nt++){
            const int col = n0 + warpN + nt*8 + 2*t4;
            const float bv0 = bias[col], bv1 = bias[col+1];
            const float a0 = acc[mt][nt][0] + bv0, a1 = acc[mt][nt][1] + bv1;
            const float a2 = acc[mt][nt][2] + bv0, a3 = acc[mt][nt][3] + bv1;
            if (SPLIT_OUT){
                unsigned hw0 = pack2(a0, a1);
                unsigned lw0 = pack2(a0 - __uint_as_float(hw0 << 16),
                                     a1 - __uint_as_float(hw0 & 0xffff0000u));
                unsigned hw1 = pack2(a2, a3);
                unsigned lw1 = pack2(a2 - __uint_as_float(hw1 << 16),
                                     a3 - __uint_as_float(hw1 & 0xffff0000u));
                *(unsigned*)(Ch + (size_t)row    *N + col) = hw0;
                *(unsigned*)(Cl + (size_t)row    *N + col) = lw0;
                *(unsigned*)(Ch + (size_t)(row+8)*N + col) = hw1;
                *(unsigned*)(Cl + (size_t)(row+8)*N + col) = lw1;
            } else {
                *(float2*)(C + (size_t)row    *N + col) = make_float2(a0, a1);
                *(float2*)(C + (size_t)(row+8)*N + col) = make_float2(a2, a3);
            }
        }
    }
}

// ---------------------------------------------------------------------------
// BF16 flash attention on pre-split planes. Block = 64 q-rows of one (b,h);
// 4 warps x 16 rows; 64 keys/iter; cp.async 2-stage K/V pipeline; P in regs.
// 1/sqrt(dk)=0.125 folded into S post-mma. Output written as hi/lo planes.
// ---------------------------------------------------------------------------
#define AS   72                 // bf16 elems per smem row (144B)
#define ATE  (64*AS)            // plane (4608)
#define ASTG (4*ATE)            // stage: Kh|Kl|Vh|Vl (18432)

__global__ __launch_bounds__(128) void attn_mma(
    const __nv_bfloat16* __restrict__ Qh_g, const __nv_bfloat16* __restrict__ Ql_g,
    const __nv_bfloat16* __restrict__ Kh_g, const __nv_bfloat16* __restrict__ Kl_g,
    const __nv_bfloat16* __restrict__ Vh_g, const __nv_bfloat16* __restrict__ Vl_g,
    __nv_bfloat16* __restrict__ Oh_g, __nv_bfloat16* __restrict__ Ol_g)
{
    extern __shared__ __nv_bfloat16 sb[];
    const int tid  = threadIdx.x;
    const int warp = tid >> 5, lane = tid & 31;
    const int g = lane >> 2, t4 = lane & 3;
    const int lr = lane & 7, grp = lane >> 3;
    const int qt = (int)gridDim.x - 1 - (int)blockIdx.x;   // long blocks first
    const int h = blockIdx.y, b = blockIdx.z;
    const int w16 = warp * 16;
    const size_t hoff = (size_t)h * DKH;

    // ---- Q tile -> stage0 planes 0/1 via cp.async, then fragments ----
    #pragma unroll
    for (int pl = 0; pl < 2; pl++){
        const __nv_bfloat16* base = pl ? Ql_g : Qh_g;
        #pragma unroll
        for (int j = 0; j < 4; j++){
            const int cc = j*128 + tid;
            const int r = cc >> 3, col = (cc & 7) * 8;
            cp16(sb + pl*ATE + r*AS + col,
                 base + (size_t)(b*SEQ + qt*64 + r)*DM + hoff + col);
        }
    }
    cpcommit(); cpwait<0>();
    __syncthreads();

    unsigned qh[4][4], ql[4][4];
    #pragma unroll
    for (int kc = 0; kc < 4; kc++){
        const int off = (w16 + lr + (grp&1)*8)*AS + kc*16 + (grp>>1)*8;
        ldsm4(qh[kc], sb + off);
        ldsm4(ql[kc], sb + ATE + off);
    }
    __syncthreads();   // all warps done with Q smem before K/V overwrite

    auto issue = [&](int kt){
        const int st = (kt & 1) * ASTG;
        #pragma unroll
        for (int pl = 0; pl < 4; pl++){
            const __nv_bfloat16* base = (pl==0)?Kh_g:(pl==1)?Kl_g:(pl==2)?Vh_g:Vl_g;
            #pragma unroll
            for (int j = 0; j < 4; j++){
                const int cc = j*128 + tid;
                const int r = cc >> 3, col = (cc & 7) * 8;
                cp16(sb + st + pl*ATE + r*AS + col,
                     base + (size_t)(b*SEQ + kt*64 + r)*DM + hoff + col);
            }
        }
        cpcommit();
    };

    float o[8][4];
    #pragma unroll
    for (int nn=0;nn<8;nn++)
        #pragma unroll
        for (int c=0;c<4;c++) o[nn][c] = 0.f;
    float mrow0 = -1e30f, mrow1 = -1e30f, lrow0 = 0.f, lrow1 = 0.f;

    issue(0);
    for (int kt = 0; kt <= qt; kt++){
        if (kt < qt){ issue(kt+1); cpwait<1>(); } else cpwait<0>();
        __syncthreads();

        const __nv_bfloat16* S  = sb + (kt & 1) * ASTG;
        const __nv_bfloat16* Kh = S;
        const __nv_bfloat16* Kl = S +     ATE;
        const __nv_bfloat16* Vh = S + 2 * ATE;
        const __nv_bfloat16* Vl = S + 3 * ATE;

        // ---- S = Q K^T (3xbf16) ----
        float s[8][4];
        #pragma unroll
        for (int nn=0;nn<8;nn++)
            #pragma unroll
            for (int c=0;c<4;c++) s[nn][c] = 0.f;

        #pragma unroll
        for (int kc = 0; kc < 4; kc++){
            #pragma unroll
            for (int ng = 0; ng < 4; ng++){
                unsigned kh4[4], kl4[4];
                const int off = (ng*16 + lr + (grp>>1)*8)*AS + kc*16 + (grp&1)*8;
                ldsm4(kh4, Kh + off);
                ldsm4(kl4, Kl + off);
                #pragma unroll
                for (int hf = 0; hf < 2; hf++){
                    const int nn = ng*2 + hf;
                    const unsigned b0 = kh4[2*hf], b1 = kh4[2*hf+1];
                    mma16(s[nn], qh[kc], b0, b1);
                    mma16(s[nn], ql[kc], b0, b1);
                    mma16(s[nn], qh[kc], kl4[2*hf], kl4[2*hf+1]);
                }
            }
        }

        // fold 1/sqrt(dk)
        #pragma unroll
        for (int nn = 0; nn < 8; nn++)
            #pragma unroll
            for (int c = 0; c < 4; c++) s[nn][c] *= 0.125f;

        // ---- causal mask on diagonal tile ----
        if (kt == qt){
            #pragma unroll
            for (int nn = 0; nn < 8; nn++){
                const int col = nn*8 + 2*t4;
                if (col     > w16+g  ) s[nn][0] = -1e30f;
                if (col + 1 > w16+g  ) s[nn][1] = -1e30f;
                if (col     > w16+g+8) s[nn][2] = -1e30f;
                if (col + 1 > w16+g+8) s[nn][3] = -1e30f;
            }
        }

        // ---- online softmax ----
        float mx0 = -1e30f, mx1 = -1e30f;
        #pragma unroll
        for (int nn = 0; nn < 8; nn++){
            mx0 = fmaxf(mx0, fmaxf(s[nn][0], s[nn][1]));
            mx1 = fmaxf(mx1, fmaxf(s[nn][2], s[nn][3]));
        }
        mx0 = fmaxf(mx0, __shfl_xor_sync(0xffffffffu, mx0, 1));
        mx0 = fmaxf(mx0, __shfl_xor_sync(0xffffffffu, mx0, 2));
        mx1 = fmaxf(mx1, __shfl_xor_sync(0xffffffffu, mx1, 1));
        mx1 = fmaxf(mx1, __shfl_xor_sync(0xffffffffu, mx1, 2));

        const float mn0 = fmaxf(mrow0, mx0), mn1 = fmaxf(mrow1, mx1);
        const float cr0 = __expf(mrow0 - mn0), cr1 = __expf(mrow1 - mn1);
        lrow0 *= cr0; lrow1 *= cr1;
        #pragma unroll
        for (int nn = 0; nn < 8; nn++){
            o[nn][0] *= cr0; o[nn][1] *= cr0;
            o[nn][2] *= cr1; o[nn][3] *= cr1;
        }
        mrow0 = mn0; mrow1 = mn1;

        #pragma unroll
        for (int nn = 0; nn < 8; nn++){
            const float p0 = __expf(s[nn][0] - mn0);
            const float p1 = __expf(s[nn][1] - mn0);
            const float p2 = __expf(s[nn][2] - mn1);
            const float p3 = __expf(s[nn][3] - mn1);
            lrow0 += p0 + p1;
            lrow1 += p2 + p3;
            s[nn][0] = p0; s[nn][1] = p1; s[nn][2] = p2; s[nn][3] = p3;
        }

        // ---- O += P V (P hi/lo in regs, V via ldmatrix.trans) ----
        #pragma unroll
        for (int kc = 0; kc < 4; kc++){
            const float* sA = s[2*kc];
            const float* sB = s[2*kc+1];
            unsigned ph[4], pl4[4];
            ph[0] = pack2(sA[0], sA[1]);
            ph[1] = pack2(sA[2], sA[3]);
            ph[2] = pack2(sB[0], sB[1]);
            ph[3] = pack2(sB[2], sB[3]);
            #pragma unroll
            for (int r = 0; r < 4; r++){
                const float* sp = (r < 2) ? sA : sB;
                const int e = (r & 1) * 2;
                const float h0f = __uint_as_float(ph[r] << 16);
                const float h1f = __uint_as_float(ph[r] & 0xffff0000u);
                pl4[r] = pack2(sp[e] - h0f, sp[e+1] - h1f);
            }
            #pragma unroll
            for (int dt = 0; dt < 4; dt++){
                unsigned vh4[4], vl4[4];
                const int off = (kc*16 + lr + (grp&1)*8)*AS + dt*16 + (grp>>1)*8;
                ldsm4t(vh4, Vh + off);
                ldsm4t(vl4, Vl + off);
                #pragma unroll
                for (int hf = 0; hf < 2; hf++){
                    const int nd = dt*2 + hf;
                    const unsigned b0 = vh4[2*hf], b1 = vh4[2*hf+1];
                    mma16(o[nd], ph, b0, b1);
                    mma16(o[nd], ph, vl4[2*hf], vl4[2*hf+1]);
                    mma16(o[nd], pl4, b0, b1);
                }
            }
        }
        __syncthreads();   // all warps done reading this stage
    }

    // ---- final normalize + split-store ----
    lrow0 += __shfl_xor_sync(0xffffffffu, lrow0, 1);
    lrow0 += __shfl_xor_sync(0xffffffffu, lrow0, 2);
    lrow1 += __shfl_xor_sync(0xffffffffu, lrow1, 1);
    lrow1 += __shfl_xor_sync(0xffffffffu, lrow1, 2);
    const float inv0 = 1.f / lrow0, inv1 = 1.f / lrow1;

    const int rowg = b*SEQ + qt*64 + w16 + g;
    const size_t base0 = (size_t)rowg    *DM + hoff;
    const size_t base1 = (size_t)(rowg+8)*DM + hoff;
    #pragma unroll
    for (int nn = 0; nn < 8; nn++){
        const int col = nn*8 + 2*t4;
        const float a0 = o[nn][0]*inv0, a1 = o[nn][1]*inv0;
        const float a2 = o[nn][2]*inv1, a3 = o[nn][3]*inv1;
        unsigned hw0 = pack2(a0, a1);
        unsigned lw0 = pack2(a0 - __uint_as_float(hw0 << 16),
                             a1 - __uint_as_float(hw0 & 0xffff0000u));
        unsigned hw1 = pack2(a2, a3);
        unsigned lw1 = pack2(a2 - __uint_as_float(hw1 << 16),
                             a3 - __uint_as_float(hw1 & 0xffff0000u));
        *(unsigned*)(Oh_g + base0 + col) = hw0;
        *(unsigned*)(Ol_g + base0 + col) = lw0;
        *(unsigned*)(Oh_g + base1 + col) = hw1;
        *(unsigned*)(Ol_g + base1 + col) = lw1;
    }
}

// ---------------------------------------------------------------------------
extern "C" void kernel_launch(void* const* d_in, const int* in_sizes, int n_in,
                              void* d_out, int out_size)
{
    const float* q   = (const float*)d_in[0];
    const float* k   = (const float*)d_in[1];
    const float* v   = (const float*)d_in[2];
    // d_in[3]: causal mask (tril) — computed analytically in-kernel.
    const float* w_q = (const float*)d_in[4];
    const float* b_q = (const float*)d_in[5];
    const float* w_k = (const float*)d_in[6];
    const float* b_k = (const float*)d_in[7];
    const float* w_v = (const float*)d_in[8];
    const float* b_v = (const float*)d_in[9];
    const float* w_o = (const float*)d_in[10];
    const float* b_o = (const float*)d_in[11];
    float* out = (float*)d_out;

    __nv_bfloat16 *aqh,*aql,*akh,*akl,*avh,*avl;
    __nv_bfloat16 *wqh,*wql,*wkh,*wkl,*wvh,*wvl,*woh,*wol;
    __nv_bfloat16 *Qh,*Ql,*Kh,*Kl,*Vh,*Vl,*Oh,*Ol;
    cudaGetSymbolAddress((void**)&aqh, g_aqh); cudaGetSymbolAddress((void**)&aql, g_aql);
    cudaGetSymbolAddress((void**)&akh, g_akh); cudaGetSymbolAddress((void**)&akl, g_akl);
    cudaGetSymbolAddress((void**)&avh, g_avh); cudaGetSymbolAddress((void**)&avl, g_avl);
    cudaGetSymbolAddress((void**)&wqh, g_wqh); cudaGetSymbolAddress((void**)&wql, g_wql);
    cudaGetSymbolAddress((void**)&wkh, g_wkh); cudaGetSymbolAddress((void**)&wkl, g_wkl);
    cudaGetSymbolAddress((void**)&wvh, g_wvh); cudaGetSymbolAddress((void**)&wvl, g_wvl);
    cudaGetSymbolAddress((void**)&woh, g_woh); cudaGetSymbolAddress((void**)&wol, g_wol);
    cudaGetSymbolAddress((void**)&Qh,  g_Qh ); cudaGetSymbolAddress((void**)&Ql,  g_Ql );
    cudaGetSymbolAddress((void**)&Kh,  g_Kh ); cudaGetSymbolAddress((void**)&Kl,  g_Kl );
    cudaGetSymbolAddress((void**)&Vh,  g_Vh ); cudaGetSymbolAddress((void**)&Vl,  g_Vl );
    cudaGetSymbolAddress((void**)&Oh,  g_Oh ); cudaGetSymbolAddress((void**)&Ol,  g_Ol );

    const int gemm_smem = 2 * GSTG * (int)sizeof(__nv_bfloat16);   // 81920
    const int attn_smem = 2 * ASTG * (int)sizeof(__nv_bfloat16);   // 73728
    cudaFuncSetAttribute(gemm3s<true>,  cudaFuncAttributeMaxDynamicSharedMemorySize, gemm_smem);
    cudaFuncSetAttribute(gemm3s<false>, cudaFuncAttributeMaxDynamicSharedMemorySize, gemm_smem);
    cudaFuncSetAttribute(attn_mma,      cudaFuncAttributeMaxDynamicSharedMemorySize, attn_smem);

    // ---- pre-split inputs + weights ----
    const int n4i = NELEM / 4, n4w = WELEM / 4;
    split_planes<<<n4i/256, 256>>>((const float4*)q, (uint2*)aqh, (uint2*)aql, n4i);
    split_planes<<<n4i/256, 256>>>((const float4*)k, (uint2*)akh, (uint2*)akl, n4i);
    split_planes<<<n4i/256, 256>>>((const float4*)v, (uint2*)avh, (uint2*)avl, n4i);
    split_planes<<<n4w/256, 256>>>((const float4*)w_q, (uint2*)wqh, (uint2*)wql, n4w);
    split_planes<<<n4w/256, 256>>>((const float4*)w_k, (uint2*)wkh, (uint2*)wkl, n4w);
    split_planes<<<n4w/256, 256>>>((const float4*)w_v, (uint2*)wvh, (uint2*)wvl, n4w);
    split_planes<<<n4w/256, 256>>>((const float4*)w_o, (uint2*)woh, (uint2*)wol, n4w);

    dim3 ggrid(DM / 128, MROWS / 128);   // (8, 64)
    gemm3s<true><<<ggrid, 256, gemm_smem>>>(aqh, aql, wqh, wql, b_q, nullptr, Qh, Ql, MROWS, DM, DM);
    gemm3s<true><<<ggrid, 256, gemm_smem>>>(akh, akl, wkh, wkl, b_k, nullptr, Kh, Kl, MROWS, DM, DM);
    gemm3s<true><<<ggrid, 256, gemm_smem>>>(avh, avl, wvh, wvl, b_v, nullptr, Vh, Vl, MROWS, DM, DM);

    dim3 agrid(SEQ / 64, NH, BATCH);     // (32, 16, 4)
    attn_mma<<<agrid, 128, attn_smem>>>(Qh, Ql, Kh, Kl, Vh, Vl, Oh, Ol);

    gemm3s<false><<<ggrid, 256, gemm_smem>>>(Oh, Ol, woh, wol, b_o, out, nullptr, nullptr, MROWS, DM, DM);
}

// round 8
// speedup vs baseline: 5.3251x; 1.0507x over previous
#include <cuda_runtime.h>
#include <cuda_bf16.h>

#define BATCH 4
#define SEQ   2048
#define DM    1024
#define NH    16
#define DKH   64
#define MROWS (BATCH*SEQ)      // 8192
#define NELEM (MROWS*DM)       // 8388608
#define WELEM (DM*DM)          // 1048576

// ---------------------------------------------------------------------------
// Scratch planes (device globals: allocation-free per harness rules)
// ---------------------------------------------------------------------------
__device__ __nv_bfloat16 g_aqh[NELEM], g_aql[NELEM];   // split q input
__device__ __nv_bfloat16 g_akh[NELEM], g_akl[NELEM];   // split k input
__device__ __nv_bfloat16 g_avh[NELEM], g_avl[NELEM];   // split v input
__device__ __nv_bfloat16 g_wqh[WELEM], g_wql[WELEM];
__device__ __nv_bfloat16 g_wkh[WELEM], g_wkl[WELEM];
__device__ __nv_bfloat16 g_wvh[WELEM], g_wvl[WELEM];
__device__ __nv_bfloat16 g_woh[WELEM], g_wol[WELEM];
__device__ __nv_bfloat16 g_Qh[NELEM],  g_Ql[NELEM];    // projected Q planes
__device__ __nv_bfloat16 g_Kh[NELEM],  g_Kl[NELEM];
__device__ __nv_bfloat16 g_Vh[NELEM],  g_Vl[NELEM];
__device__ __nv_bfloat16 g_Oh[NELEM],  g_Ol[NELEM];    // attention out planes

// ---------------------------------------------------------------------------
// helpers
// ---------------------------------------------------------------------------
__device__ __forceinline__ unsigned pack2(float e0, float e1){
    unsigned r; asm("cvt.rn.bf16x2.f32 %0, %1, %2;" : "=r"(r) : "f"(e1), "f"(e0));
    return r;   // lo half = bf16(e0), hi half = bf16(e1)
}
__device__ __forceinline__ void split4(float4 v, unsigned &h0, unsigned &h1,
                                       unsigned &l0, unsigned &l1){
    h0 = pack2(v.x, v.y);
    h1 = pack2(v.z, v.w);
    float hx = __uint_as_float(h0 << 16);
    float hy = __uint_as_float(h0 & 0xffff0000u);
    float hz = __uint_as_float(h1 << 16);
    float hw = __uint_as_float(h1 & 0xffff0000u);
    l0 = pack2(v.x - hx, v.y - hy);
    l1 = pack2(v.z - hz, v.w - hw);
}
__device__ __forceinline__ void mma16(float c[4], const unsigned a[4],
                                      unsigned b0, unsigned b1){
    asm volatile("mma.sync.aligned.m16n8k16.row.col.f32.bf16.bf16.f32 "
        "{%0,%1,%2,%3},{%4,%5,%6,%7},{%8,%9},{%0,%1,%2,%3};\n"
        : "+f"(c[0]),"+f"(c[1]),"+f"(c[2]),"+f"(c[3])
        : "r"(a[0]),"r"(a[1]),"r"(a[2]),"r"(a[3]),"r"(b0),"r"(b1));
}
__device__ __forceinline__ void ldsm4(unsigned r[4], const void* p){
    unsigned addr = (unsigned)__cvta_generic_to_shared(p);
    asm volatile("ldmatrix.sync.aligned.m8n8.x4.shared.b16 {%0,%1,%2,%3},[%4];"
        : "=r"(r[0]),"=r"(r[1]),"=r"(r[2]),"=r"(r[3]) : "r"(addr));
}
__device__ __forceinline__ void ldsm4t(unsigned r[4], const void* p){
    unsigned addr = (unsigned)__cvta_generic_to_shared(p);
    asm volatile("ldmatrix.sync.aligned.m8n8.x4.trans.shared.b16 {%0,%1,%2,%3},[%4];"
        : "=r"(r[0]),"=r"(r[1]),"=r"(r[2]),"=r"(r[3]) : "r"(addr));
}
__device__ __forceinline__ void cp16(const void* smem_dst, const void* gmem_src){
    unsigned d = (unsigned)__cvta_generic_to_shared(smem_dst);
    asm volatile("cp.async.cg.shared.global [%0],[%1],16;" :: "r"(d), "l"(gmem_src));
}
__device__ __forceinline__ void cpcommit(){ asm volatile("cp.async.commit_group;"); }
template<int N> __device__ __forceinline__ void cpwait(){
    asm volatile("cp.async.wait_group %0;" :: "n"(N));
}

// ---------------------------------------------------------------------------
// split kernel: fp32 -> bf16 hi/lo planes.  4 coalesced float4 per thread.
// ---------------------------------------------------------------------------
__global__ __launch_bounds__(256) void split_planes(
    const float4* __restrict__ x, uint2* __restrict__ hi, uint2* __restrict__ lo, int n4)
{
    const int base = blockIdx.x * (blockDim.x * 4) + threadIdx.x;
    float4 v[4];
    #pragma unroll
    for (int j = 0; j < 4; j++){
        const int i = base + j * blockDim.x;
        if (i < n4) v[j] = x[i];
    }
    #pragma unroll
    for (int j = 0; j < 4; j++){
        const int i = base + j * blockDim.x;
        if (i < n4){
            unsigned h0,h1,l0,l1;
            split4(v[j], h0,h1,l0,l1);
            hi[i] = make_uint2(h0,h1);
            lo[i] = make_uint2(l0,l1);
        }
    }
}

// ---------------------------------------------------------------------------
// 3xBF16 GEMM on pre-split operands. C[m,n] = sum_k A[m,k]*W[n,k] + bias[n].
// 128x128x32 tiles, 256 thr, 8 warps (64x32), cp.async 2-stage pipeline.
// Fused variant: gridDim.z selects one of three argument sets (QKV).
// ---------------------------------------------------------------------------
#define GS2  40                 // bf16 elems per smem row (80B)
#define GPL  (128*GS2)          // elems per plane (5120)
#define GSTG (4*GPL)            // stage: Ah|Al|Bh|Bl (20480)

struct GemmArgs {
    const __nv_bfloat16 *Ah, *Al, *Bh, *Bl;
    const float* bias;
    float* C;
    __nv_bfloat16 *Ch, *Cl;
};

template<bool SPLIT_OUT>
__device__ __forceinline__ void gemm3s_body(const GemmArgs& ga, int M, int N, int K)
{
    extern __shared__ __nv_bfloat16 smb[];
    const int tid  = threadIdx.x;
    const int warp = tid >> 5, lane = tid & 31;
    const int g = lane >> 2, t4 = lane & 3;
    const int lr = lane & 7, grp = lane >> 3;
    const int warpM = (warp >> 2) * 64;
    const int warpN = (warp & 3) * 32;
    const int m0 = blockIdx.y * 128, n0 = blockIdx.x * 128;

    float acc[4][4][4];
    #pragma unroll
    for (int i=0;i<4;i++)
        #pragma unroll
        for (int j=0;j<4;j++)
            #pragma unroll
            for (int c=0;c<4;c++) acc[i][j][c] = 0.f;

    auto issue = [&](int kt){
        const int st = (kt & 1) * GSTG;
        #pragma unroll
        for (int pl = 0; pl < 4; pl++){
            const __nv_bfloat16* base = (pl==0)?ga.Ah:(pl==1)?ga.Al:(pl==2)?ga.Bh:ga.Bl;
            const int rb = (pl < 2) ? m0 : n0;
            #pragma unroll
            for (int j = 0; j < 2; j++){
                const int cc = j*256 + tid;
                const int r = cc >> 2, col = (cc & 3) * 8;
                cp16(smb + st + pl*GPL + r*GS2 + col,
                     base + (size_t)(rb + r)*K + kt*32 + col);
            }
        }
        cpcommit();
    };

    const int KT = K >> 5;
    issue(0);

    for (int kt = 0; kt < KT; kt++){
        if (kt + 1 < KT){ issue(kt+1); cpwait<1>(); } else cpwait<0>();
        __syncthreads();

        const __nv_bfloat16* S   = smb + (kt & 1) * GSTG;
        const __nv_bfloat16* SAh = S;
        const __nv_bfloat16* SAl = S +     GPL;
        const __nv_bfloat16* SBh = S + 2 * GPL;
        const __nv_bfloat16* SBl = S + 3 * GPL;

        #pragma unroll
        for (int kc = 0; kc < 2; kc++){
            unsigned bh[2][4], bl[2][4];
            #pragma unroll
            for (int ng = 0; ng < 2; ng++){
                const int off = (warpN + ng*16 + lr + (grp>>1)*8)*GS2 + kc*16 + (grp&1)*8;
                ldsm4(bh[ng], SBh + off);
                ldsm4(bl[ng], SBl + off);
            }
            #pragma unroll
            for (int mt = 0; mt < 4; mt++){
                const int off = (warpM + mt*16 + lr + (grp&1)*8)*GS2 + kc*16 + (grp>>1)*8;
                unsigned ah[4], al[4];
                ldsm4(ah, SAh + off);
                ldsm4(al, SAl + off);
                #pragma unroll
                for (int ng = 0; ng < 2; ng++)
                    #pragma unroll
                    for (int hf = 0; hf < 2; hf++){
                        const int nt = ng*2 + hf;
                        const unsigned b0 = bh[ng][2*hf], b1 = bh[ng][2*hf+1];
                        mma16(acc[mt][nt], ah, b0, b1);
                        mma16(acc[mt][nt], al, b0, b1);
                        mma16(acc[mt][nt], ah, bl[ng][2*hf], bl[ng][2*hf+1]);
                    }
            }
        }
        __syncthreads();
    }

    #pragma unroll
    for (int mt = 0; mt < 4; mt++){
        const int row = m0 + warpM + mt*16 + g;
        #pragma unroll
        for (int nt = 0; nt < 4; nt++){
            const int col = n0 + warpN + nt*8 + 2*t4;
            const float bv0 = ga.bias[col], bv1 = ga.bias[col+1];
            const float a0 = acc[mt][nt][0] + bv0, a1 = acc[mt][nt][1] + bv1;
            const float a2 = acc[mt][nt][2] + bv0, a3 = acc[mt][nt][3] + bv1;
            if (SPLIT_OUT){
                unsigned hw0 = pack2(a0, a1);
                unsigned lw0 = pack2(a0 - __uint_as_float(hw0 << 16),
                                     a1 - __uint_as_float(hw0 & 0xffff0000u));
                unsigned hw1 = pack2(a2, a3);
                unsigned lw1 = pack2(a2 - __uint_as_float(hw1 << 16),
                                     a3 - __uint_as_float(hw1 & 0xffff0000u));
                *(unsigned*)(ga.Ch + (size_t)row    *N + col) = hw0;
                *(unsigned*)(ga.Cl + (size_t)row    *N + col) = lw0;
                *(unsigned*)(ga.Ch + (size_t)(row+8)*N + col) = hw1;
                *(unsigned*)(ga.Cl + (size_t)(row+8)*N + col) = lw1;
            } else {
                *(float2*)(ga.C + (size_t)row    *N + col) = make_float2(a0, a1);
                *(float2*)(ga.C + (size_t)(row+8)*N + col) = make_float2(a2, a3);
            }
        }
    }
}

__global__ __launch_bounds__(256, 2) void gemm3s_qkv(
    GemmArgs a0, GemmArgs a1, GemmArgs a2, int M, int N, int K)
{
    const GemmArgs& ga = (blockIdx.z == 0) ? a0 : (blockIdx.z == 1) ? a1 : a2;
    gemm3s_body<true>(ga, M, N, K);
}
__global__ __launch_bounds__(256, 2) void gemm3s_out(
    GemmArgs ga, int M, int N, int K)
{
    gemm3s_body<false>(ga, M, N, K);
}

// ---------------------------------------------------------------------------
// BF16 flash attention on pre-split planes. Block = 128 q-rows of one (b,h);
// 8 warps x 16 rows; 64 keys/iter; cp.async 2-stage K/V pipeline; P in regs.
// ---------------------------------------------------------------------------
#define AS   72                 // bf16 elems per smem row (144B)
#define ATE  (64*AS)            // K/V plane (4608)
#define ASTG (4*ATE)            // stage: Kh|Kl|Vh|Vl (18432)
#define QPL  (128*AS)           // transient Q plane (9216)

__global__ __launch_bounds__(256, 2) void attn_mma(
    const __nv_bfloat16* __restrict__ Qh_g, const __nv_bfloat16* __restrict__ Ql_g,
    const __nv_bfloat16* __restrict__ Kh_g, const __nv_bfloat16* __restrict__ Kl_g,
    const __nv_bfloat16* __restrict__ Vh_g, const __nv_bfloat16* __restrict__ Vl_g,
    __nv_bfloat16* __restrict__ Oh_g, __nv_bfloat16* __restrict__ Ol_g)
{
    extern __shared__ __nv_bfloat16 sb[];
    const int tid  = threadIdx.x;
    const int warp = tid >> 5, lane = tid & 31;
    const int g = lane >> 2, t4 = lane & 3;
    const int lr = lane & 7, grp = lane >> 3;
    const int qb = (int)gridDim.x - 1 - (int)blockIdx.x;   // long blocks first
    const int h = blockIdx.y, b = blockIdx.z;
    const int w16 = warp * 16;
    const int qrow0 = qb * 128;                // first q row of this block
    const size_t hoff = (size_t)h * DKH;

    // ---- Q tile (128 rows) -> transient smem planes, then fragments ----
    #pragma unroll
    for (int pl = 0; pl < 2; pl++){
        const __nv_bfloat16* base = pl ? Ql_g : Qh_g;
        #pragma unroll
        for (int j = 0; j < 4; j++){
            const int cc = j*256 + tid;                    // 1024 chunks/plane
            const int r = cc >> 3, col = (cc & 7) * 8;
            cp16(sb + pl*QPL + r*AS + col,
                 base + (size_t)(b*SEQ + qrow0 + r)*DM + hoff + col);
        }
    }
    cpcommit(); cpwait<0>();
    __syncthreads();

    unsigned qh[4][4], ql[4][4];
    #pragma unroll
    for (int kc = 0; kc < 4; kc++){
        const int off = (w16 + lr + (grp&1)*8)*AS + kc*16 + (grp>>1)*8;
        ldsm4(qh[kc], sb + off);
        ldsm4(ql[kc], sb + QPL + off);
    }
    __syncthreads();   // all warps done with Q smem before K/V overwrite

    auto issue = [&](int kt){
        const int st = (kt & 1) * ASTG;
        #pragma unroll
        for (int pl = 0; pl < 4; pl++){
            const __nv_bfloat16* base = (pl==0)?Kh_g:(pl==1)?Kl_g:(pl==2)?Vh_g:Vl_g;
            #pragma unroll
            for (int j = 0; j < 2; j++){
                const int cc = j*256 + tid;                // 512 chunks/plane
                const int r = cc >> 3, col = (cc & 7) * 8;
                cp16(sb + st + pl*ATE + r*AS + col,
                     base + (size_t)(b*SEQ + kt*64 + r)*DM + hoff + col);
            }
        }
        cpcommit();
    };

    float o[8][4];
    #pragma unroll
    for (int nn=0;nn<8;nn++)
        #pragma unroll
        for (int c=0;c<4;c++) o[nn][c] = 0.f;
    float mrow0 = -1e30f, mrow1 = -1e30f, lrow0 = 0.f, lrow1 = 0.f;

    const int nkt = 2*qb + 2;   // key tiles of 64 covering [0, qrow0+128)
    issue(0);
    for (int kt = 0; kt < nkt; kt++){
        if (kt + 1 < nkt){ issue(kt+1); cpwait<1>(); } else cpwait<0>();
        __syncthreads();

        const __nv_bfloat16* S  = sb + (kt & 1) * ASTG;
        const __nv_bfloat16* Kh = S;
        const __nv_bfloat16* Kl = S +     ATE;
        const __nv_bfloat16* Vh = S + 2 * ATE;
        const __nv_bfloat16* Vl = S + 3 * ATE;

        // ---- S = Q K^T (3xbf16) ----
        float s[8][4];
        #pragma unroll
        for (int nn=0;nn<8;nn++)
            #pragma unroll
            for (int c=0;c<4;c++) s[nn][c] = 0.f;

        #pragma unroll
        for (int kc = 0; kc < 4; kc++){
            #pragma unroll
            for (int ng = 0; ng < 4; ng++){
                unsigned kh4[4], kl4[4];
                const int off = (ng*16 + lr + (grp>>1)*8)*AS + kc*16 + (grp&1)*8;
                ldsm4(kh4, Kh + off);
                ldsm4(kl4, Kl + off);
                #pragma unroll
                for (int hf = 0; hf < 2; hf++){
                    const int nn = ng*2 + hf;
                    const unsigned b0 = kh4[2*hf], b1 = kh4[2*hf+1];
                    mma16(s[nn], qh[kc], b0, b1);
                    mma16(s[nn], ql[kc], b0, b1);
                    mma16(s[nn], qh[kc], kl4[2*hf], kl4[2*hf+1]);
                }
            }
        }

        // fold 1/sqrt(dk)
        #pragma unroll
        for (int nn = 0; nn < 8; nn++)
            #pragma unroll
            for (int c = 0; c < 4; c++) s[nn][c] *= 0.125f;

        // ---- causal mask (only tiles crossing this warp's diagonal) ----
        if (kt*64 + 63 > qrow0 + w16){
            const int r0 = qrow0 + w16 + g;
            #pragma unroll
            for (int nn = 0; nn < 8; nn++){
                const int col = kt*64 + nn*8 + 2*t4;
                if (col     > r0    ) s[nn][0] = -1e30f;
                if (col + 1 > r0    ) s[nn][1] = -1e30f;
                if (col     > r0 + 8) s[nn][2] = -1e30f;
                if (col + 1 > r0 + 8) s[nn][3] = -1e30f;
            }
        }

        // ---- online softmax ----
        float mx0 = -1e30f, mx1 = -1e30f;
        #pragma unroll
        for (int nn = 0; nn < 8; nn++){
            mx0 = fmaxf(mx0, fmaxf(s[nn][0], s[nn][1]));
            mx1 = fmaxf(mx1, fmaxf(s[nn][2], s[nn][3]));
        }
        mx0 = fmaxf(mx0, __shfl_xor_sync(0xffffffffu, mx0, 1));
        mx0 = fmaxf(mx0, __shfl_xor_sync(0xffffffffu, mx0, 2));
        mx1 = fmaxf(mx1, __shfl_xor_sync(0xffffffffu, mx1, 1));
        mx1 = fmaxf(mx1, __shfl_xor_sync(0xffffffffu, mx1, 2));

        const float mn0 = fmaxf(mrow0, mx0), mn1 = fmaxf(mrow1, mx1);
        const float cr0 = __expf(mrow0 - mn0), cr1 = __expf(mrow1 - mn1);
        lrow0 *= cr0; lrow1 *= cr1;
        #pragma unroll
        for (int nn = 0; nn < 8; nn++){
            o[nn][0] *= cr0; o[nn][1] *= cr0;
            o[nn][2] *= cr1; o[nn][3] *= cr1;
        }
        mrow0 = mn0; mrow1 = mn1;

        #pragma unroll
        for (int nn = 0; nn < 8; nn++){
            const float p0 = __expf(s[nn][0] - mn0);
            const float p1 = __expf(s[nn][1] - mn0);
            const float p2 = __expf(s[nn][2] - mn1);
            const float p3 = __expf(s[nn][3] - mn1);
            lrow0 += p0 + p1;
            lrow1 += p2 + p3;
            s[nn][0] = p0; s[nn][1] = p1; s[nn][2] = p2; s[nn][3] = p3;
        }

        // ---- O += P V (P hi/lo in regs, V via ldmatrix.trans) ----
        #pragma unroll
        for (int kc = 0; kc < 4; kc++){
            const float* sA = s[2*kc];
            const float* sB = s[2*kc+1];
            unsigned ph[4], pl4[4];
            ph[0] = pack2(sA[0], sA[1]);
            ph[1] = pack2(sA[2], sA[3]);
            ph[2] = pack2(sB[0], sB[1]);
            ph[3] = pack2(sB[2], sB[3]);
            #pragma unroll
            for (int r = 0; r < 4; r++){
                const float* sp = (r < 2) ? sA : sB;
                const int e = (r & 1) * 2;
                const float h0f = __uint_as_float(ph[r] << 16);
                const float h1f = __uint_as_float(ph[r] & 0xffff0000u);
                pl4[r] = pack2(sp[e] - h0f, sp[e+1] - h1f);
            }
            #pragma unroll
            for (int dt = 0; dt < 4; dt++){
                unsigned vh4[4], vl4[4];
                const int off = (kc*16 + lr + (grp&1)*8)*AS + dt*16 + (grp>>1)*8;
                ldsm4t(vh4, Vh + off);
                ldsm4t(vl4, Vl + off);
                #pragma unroll
                for (int hf = 0; hf < 2; hf++){
                    const int nd = dt*2 + hf;
                    const unsigned b0 = vh4[2*hf], b1 = vh4[2*hf+1];
                    mma16(o[nd], ph, b0, b1);
                    mma16(o[nd], ph, vl4[2*hf], vl4[2*hf+1]);
                    mma16(o[nd], pl4, b0, b1);
                }
            }
        }
        __syncthreads();   // all warps done reading this stage
    }

    // ---- final normalize + split-store ----
    lrow0 += __shfl_xor_sync(0xffffffffu, lrow0, 1);
    lrow0 += __shfl_xor_sync(0xffffffffu, lrow0, 2);
    lrow1 += __shfl_xor_sync(0xffffffffu, lrow1, 1);
    lrow1 += __shfl_xor_sync(0xffffffffu, lrow1, 2);
    const float inv0 = 1.f / lrow0, inv1 = 1.f / lrow1;

    const int rowg = b*SEQ + qrow0 + w16 + g;
    const size_t base0 = (size_t)rowg    *DM + hoff;
    const size_t base1 = (size_t)(rowg+8)*DM + hoff;
    #pragma unroll
    for (int nn = 0; nn < 8; nn++){
        const int col = nn*8 + 2*t4;
        const float a0 = o[nn][0]*inv0, a1 = o[nn][1]*inv0;
        const float a2 = o[nn][2]*inv1, a3 = o[nn][3]*inv1;
        unsigned hw0 = pack2(a0, a1);
        unsigned lw0 = pack2(a0 - __uint_as_float(hw0 << 16),
                             a1 - __uint_as_float(hw0 & 0xffff0000u));
        unsigned hw1 = pack2(a2, a3);
        unsigned lw1 = pack2(a2 - __uint_as_float(hw1 << 16),
                             a3 - __uint_as_float(hw1 & 0xffff0000u));
        *(unsigned*)(Oh_g + base0 + col) = hw0;
        *(unsigned*)(Ol_g + base0 + col) = lw0;
        *(unsigned*)(Oh_g + base1 + col) = hw1;
        *(unsigned*)(Ol_g + base1 + col) = lw1;
    }
}

// ---------------------------------------------------------------------------
extern "C" void kernel_launch(void* const* d_in, const int* in_sizes, int n_in,
                              void* d_out, int out_size)
{
    const float* q   = (const float*)d_in[0];
    const float* k   = (const float*)d_in[1];
    const float* v   = (const float*)d_in[2];
    // d_in[3]: causal mask (tril) — computed analytically in-kernel.
    const float* w_q = (const float*)d_in[4];
    const float* b_q = (const float*)d_in[5];
    const float* w_k = (const float*)d_in[6];
    const float* b_k = (const float*)d_in[7];
    const float* w_v = (const float*)d_in[8];
    const float* b_v = (const float*)d_in[9];
    const float* w_o = (const float*)d_in[10];
    const float* b_o = (const float*)d_in[11];
    float* out = (float*)d_out;

    __nv_bfloat16 *aqh,*aql,*akh,*akl,*avh,*avl;
    __nv_bfloat16 *wqh,*wql,*wkh,*wkl,*wvh,*wvl,*woh,*wol;
    __nv_bfloat16 *Qh,*Ql,*Kh,*Kl,*Vh,*Vl,*Oh,*Ol;
    cudaGetSymbolAddress((void**)&aqh, g_aqh); cudaGetSymbolAddress((void**)&aql, g_aql);
    cudaGetSymbolAddress((void**)&akh, g_akh); cudaGetSymbolAddress((void**)&akl, g_akl);
    cudaGetSymbolAddress((void**)&avh, g_avh); cudaGetSymbolAddress((void**)&avl, g_avl);
    cudaGetSymbolAddress((void**)&wqh, g_wqh); cudaGetSymbolAddress((void**)&wql, g_wql);
    cudaGetSymbolAddress((void**)&wkh, g_wkh); cudaGetSymbolAddress((void**)&wkl, g_wkl);
    cudaGetSymbolAddress((void**)&wvh, g_wvh); cudaGetSymbolAddress((void**)&wvl, g_wvl);
    cudaGetSymbolAddress((void**)&woh, g_woh); cudaGetSymbolAddress((void**)&wol, g_wol);
    cudaGetSymbolAddress((void**)&Qh,  g_Qh ); cudaGetSymbolAddress((void**)&Ql,  g_Ql );
    cudaGetSymbolAddress((void**)&Kh,  g_Kh ); cudaGetSymbolAddress((void**)&Kl,  g_Kl );
    cudaGetSymbolAddress((void**)&Vh,  g_Vh ); cudaGetSymbolAddress((void**)&Vl,  g_Vl );
    cudaGetSymbolAddress((void**)&Oh,  g_Oh ); cudaGetSymbolAddress((void**)&Ol,  g_Ol );

    const int gemm_smem = 2 * GSTG * (int)sizeof(__nv_bfloat16);   // 81920
    const int attn_smem = 2 * ASTG * (int)sizeof(__nv_bfloat16);   // 73728
    cudaFuncSetAttribute(gemm3s_qkv, cudaFuncAttributeMaxDynamicSharedMemorySize, gemm_smem);
    cudaFuncSetAttribute(gemm3s_out, cudaFuncAttributeMaxDynamicSharedMemorySize, gemm_smem);
    cudaFuncSetAttribute(attn_mma,   cudaFuncAttributeMaxDynamicSharedMemorySize, attn_smem);

    // ---- pre-split inputs + weights (4 float4 per thread) ----
    const int n4i = NELEM / 4, n4w = WELEM / 4;
    const int bi = n4i / (256*4), bw = n4w / (256*4);
    split_planes<<<bi, 256>>>((const float4*)q,   (uint2*)aqh, (uint2*)aql, n4i);
    split_planes<<<bi, 256>>>((const float4*)k,   (uint2*)akh, (uint2*)akl, n4i);
    split_planes<<<bi, 256>>>((const float4*)v,   (uint2*)avh, (uint2*)avl, n4i);
    split_planes<<<bw, 256>>>((const float4*)w_q, (uint2*)wqh, (uint2*)wql, n4w);
    split_planes<<<bw, 256>>>((const float4*)w_k, (uint2*)wkh, (uint2*)wkl, n4w);
    split_planes<<<bw, 256>>>((const float4*)w_v, (uint2*)wvh, (uint2*)wvl, n4w);
    split_planes<<<bw, 256>>>((const float4*)w_o, (uint2*)woh, (uint2*)wol, n4w);

    // ---- fused QKV projections (grid.z picks the GEMM) ----
    GemmArgs gq = {aqh, aql, wqh, wql, b_q, nullptr, Qh, Ql};
    GemmArgs gk = {akh, akl, wkh, wkl, b_k, nullptr, Kh, Kl};
    GemmArgs gv = {avh, avl, wvh, wvl, b_v, nullptr, Vh, Vl};
    dim3 ggrid(DM / 128, MROWS / 128, 3);   // (8, 64, 3)
    gemm3s_qkv<<<ggrid, 256, gemm_smem>>>(gq, gk, gv, MROWS, DM, DM);

    dim3 agrid(SEQ / 128, NH, BATCH);       // (16, 16, 4)
    attn_mma<<<agrid, 256, attn_smem>>>(Qh, Ql, Kh, Kl, Vh, Vl, Oh, Ol);

    GemmArgs go = {Oh, Ol, woh, wol, b_o, out, nullptr, nullptr};
    dim3 ogrid(DM / 128, MROWS / 128, 1);
    gemm3s_out<<<ogrid, 256, gemm_smem>>>(go, MROWS, DM, DM);
}

// round 13
// speedup vs baseline: 6.6789x; 1.2542x over previous
#include <cuda_runtime.h>
#include <cuda_bf16.h>
#include <cuda_fp16.h>

#define BATCH 4
#define SEQ   2048
#define DM    1024
#define NH    16
#define DKH   64
#define MROWS (BATCH*SEQ)      // 8192
#define NELEM (MROWS*DM)       // 8388608
#define WELEM (DM*DM)          // 1048576

// ---------------------------------------------------------------------------
// Scratch planes (device globals: allocation-free per harness rules)
// ---------------------------------------------------------------------------
__device__ __nv_bfloat16 g_aqh[NELEM], g_aql[NELEM];   // split q input
__device__ __nv_bfloat16 g_akh[NELEM], g_akl[NELEM];   // split k input
__device__ __nv_bfloat16 g_avh[NELEM], g_avl[NELEM];   // split v input
__device__ __nv_bfloat16 g_wqh[WELEM], g_wql[WELEM];
__device__ __nv_bfloat16 g_wkh[WELEM], g_wkl[WELEM];
__device__ __nv_bfloat16 g_wvh[WELEM], g_wvl[WELEM];
__device__ __nv_bfloat16 g_woh[WELEM], g_wol[WELEM];
__device__ __half        g_Qf[NELEM];                  // projected Q (fp16, pre-scaled)
__device__ __half        g_Kf[NELEM];                  // projected K (fp16)
__device__ __half        g_Vf[NELEM];                  // projected V (fp16)
__device__ __nv_bfloat16 g_Oh[NELEM],  g_Ol[NELEM];    // attention out planes

// ---------------------------------------------------------------------------
// helpers
// ---------------------------------------------------------------------------
__device__ __forceinline__ unsigned pack2(float e0, float e1){
    unsigned r; asm("cvt.rn.bf16x2.f32 %0, %1, %2;" : "=r"(r) : "f"(e1), "f"(e0));
    return r;   // lo half = bf16(e0), hi half = bf16(e1)
}
__device__ __forceinline__ unsigned pack2h(float e0, float e1){
    unsigned r; asm("cvt.rn.f16x2.f32 %0, %1, %2;" : "=r"(r) : "f"(e1), "f"(e0));
    return r;   // lo half = f16(e0), hi half = f16(e1)
}
__device__ __forceinline__ void split4(float4 v, unsigned &h0, unsigned &h1,
                                       unsigned &l0, unsigned &l1){
    h0 = pack2(v.x, v.y);
    h1 = pack2(v.z, v.w);
    float hx = __uint_as_float(h0 << 16);
    float hy = __uint_as_float(h0 & 0xffff0000u);
    float hz = __uint_as_float(h1 << 16);
    float hw = __uint_as_float(h1 & 0xffff0000u);
    l0 = pack2(v.x - hx, v.y - hy);
    l1 = pack2(v.z - hz, v.w - hw);
}
__device__ __forceinline__ void mma16(float c[4], const unsigned a[4],
                                      unsigned b0, unsigned b1){
    asm volatile("mma.sync.aligned.m16n8k16.row.col.f32.bf16.bf16.f32 "
        "{%0,%1,%2,%3},{%4,%5,%6,%7},{%8,%9},{%0,%1,%2,%3};\n"
        : "+f"(c[0]),"+f"(c[1]),"+f"(c[2]),"+f"(c[3])
        : "r"(a[0]),"r"(a[1]),"r"(a[2]),"r"(a[3]),"r"(b0),"r"(b1));
}
__device__ __forceinline__ void mma16h(float c[4], const unsigned a[4],
                                       unsigned b0, unsigned b1){
    asm volatile("mma.sync.aligned.m16n8k16.row.col.f32.f16.f16.f32 "
        "{%0,%1,%2,%3},{%4,%5,%6,%7},{%8,%9},{%0,%1,%2,%3};\n"
        : "+f"(c[0]),"+f"(c[1]),"+f"(c[2]),"+f"(c[3])
        : "r"(a[0]),"r"(a[1]),"r"(a[2]),"r"(a[3]),"r"(b0),"r"(b1));
}
__device__ __forceinline__ void ldsm4(unsigned r[4], const void* p){
    unsigned addr = (unsigned)__cvta_generic_to_shared(p);
    asm volatile("ldmatrix.sync.aligned.m8n8.x4.shared.b16 {%0,%1,%2,%3},[%4];"
        : "=r"(r[0]),"=r"(r[1]),"=r"(r[2]),"=r"(r[3]) : "r"(addr));
}
__device__ __forceinline__ void ldsm4t(unsigned r[4], const void* p){
    unsigned addr = (unsigned)__cvta_generic_to_shared(p);
    asm volatile("ldmatrix.sync.aligned.m8n8.x4.trans.shared.b16 {%0,%1,%2,%3},[%4];"
        : "=r"(r[0]),"=r"(r[1]),"=r"(r[2]),"=r"(r[3]) : "r"(addr));
}
__device__ __forceinline__ void cp16(const void* smem_dst, const void* gmem_src){
    unsigned d = (unsigned)__cvta_generic_to_shared(smem_dst);
    asm volatile("cp.async.cg.shared.global [%0],[%1],16;" :: "r"(d), "l"(gmem_src));
}
__device__ __forceinline__ void cpcommit(){ asm volatile("cp.async.commit_group;"); }
template<int N> __device__ __forceinline__ void cpwait(){
    asm volatile("cp.async.wait_group %0;" :: "n"(N));
}

// ---------------------------------------------------------------------------
// split kernel: fp32 -> bf16 hi/lo planes.  4 coalesced float4 per thread.
// ---------------------------------------------------------------------------
__global__ __launch_bounds__(256) void split_planes(
    const float4* __restrict__ x, uint2* __restrict__ hi, uint2* __restrict__ lo, int n4)
{
    const int base = blockIdx.x * (blockDim.x * 4) + threadIdx.x;
    float4 v[4];
    #pragma unroll
    for (int j = 0; j < 4; j++){
        const int i = base + j * blockDim.x;
        if (i < n4) v[j] = x[i];
    }
    #pragma unroll
    for (int j = 0; j < 4; j++){
        const int i = base + j * blockDim.x;
        if (i < n4){
            unsigned h0,h1,l0,l1;
            split4(v[j], h0,h1,l0,l1);
            hi[i] = make_uint2(h0,h1);
            lo[i] = make_uint2(l0,l1);
        }
    }
}

// ---------------------------------------------------------------------------
// 3xBF16 GEMM on pre-split operands. C[m,n] = sum_k A[m,k]*W[n,k] + bias[n].
// 128x128x32 tiles, 256 thr, 8 warps (64x32), cp.async 2-stage pipeline.
// OMODE 0: fp32 C.  OMODE 1: fp16 single plane Cf, scaled by ga.scale.
// ---------------------------------------------------------------------------
#define GS2  40                 // bf16 elems per smem row (80B)
#define GPL  (128*GS2)          // elems per plane (5120)
#define GSTG (4*GPL)            // stage: Ah|Al|Bh|Bl (20480)

struct GemmArgs {
    const __nv_bfloat16 *Ah, *Al, *Bh, *Bl;
    const float* bias;
    float* C;
    __half* Cf;
    float scale;
};

template<int OMODE>
__device__ __forceinline__ void gemm3s_body(const GemmArgs& ga, int M, int N, int K)
{
    extern __shared__ __nv_bfloat16 smb[];
    const int tid  = threadIdx.x;
    const int warp = tid >> 5, lane = tid & 31;
    const int g = lane >> 2, t4 = lane & 3;
    const int lr = lane & 7, grp = lane >> 3;
    const int warpM = (warp >> 2) * 64;
    const int warpN = (warp & 3) * 32;
    const int m0 = blockIdx.y * 128, n0 = blockIdx.x * 128;

    float acc[4][4][4];
    #pragma unroll
    for (int i=0;i<4;i++)
        #pragma unroll
        for (int j=0;j<4;j++)
            #pragma unroll
            for (int c=0;c<4;c++) acc[i][j][c] = 0.f;

    auto issue = [&](int kt){
        const int st = (kt & 1) * GSTG;
        #pragma unroll
        for (int pl = 0; pl < 4; pl++){
            const __nv_bfloat16* base = (pl==0)?ga.Ah:(pl==1)?ga.Al:(pl==2)?ga.Bh:ga.Bl;
            const int rb = (pl < 2) ? m0 : n0;
            #pragma unroll
            for (int j = 0; j < 2; j++){
                const int cc = j*256 + tid;
                const int r = cc >> 2, col = (cc & 3) * 8;
                cp16(smb + st + pl*GPL + r*GS2 + col,
                     base + (size_t)(rb + r)*K + kt*32 + col);
            }
        }
        cpcommit();
    };

    const int KT = K >> 5;
    issue(0);

    for (int kt = 0; kt < KT; kt++){
        if (kt + 1 < KT){ issue(kt+1); cpwait<1>(); } else cpwait<0>();
        __syncthreads();

        const __nv_bfloat16* S   = smb + (kt & 1) * GSTG;
        const __nv_bfloat16* SAh = S;
        const __nv_bfloat16* SAl = S +     GPL;
        const __nv_bfloat16* SBh = S + 2 * GPL;
        const __nv_bfloat16* SBl = S + 3 * GPL;

        #pragma unroll
        for (int kc = 0; kc < 2; kc++){
            unsigned bh[2][4], bl[2][4];
            #pragma unroll
            for (int ng = 0; ng < 2; ng++){
                const int off = (warpN + ng*16 + lr + (grp>>1)*8)*GS2 + kc*16 + (grp&1)*8;
                ldsm4(bh[ng], SBh + off);
                ldsm4(bl[ng], SBl + off);
            }
            #pragma unroll
            for (int mt = 0; mt < 4; mt++){
                const int off = (warpM + mt*16 + lr + (grp&1)*8)*GS2 + kc*16 + (grp>>1)*8;
                unsigned ah[4], al[4];
                ldsm4(ah, SAh + off);
                ldsm4(al, SAl + off);
                #pragma unroll
                for (int ng = 0; ng < 2; ng++)
                    #pragma unroll
                    for (int hf = 0; hf < 2; hf++){
                        const int nt = ng*2 + hf;
                        const unsigned b0 = bh[ng][2*hf], b1 = bh[ng][2*hf+1];
                        mma16(acc[mt][nt], ah, b0, b1);
                        mma16(acc[mt][nt], al, b0, b1);
                        mma16(acc[mt][nt], ah, bl[ng][2*hf], bl[ng][2*hf+1]);
                    }
            }
        }
        __syncthreads();
    }

    #pragma unroll
    for (int mt = 0; mt < 4; mt++){
        const int row = m0 + warpM + mt*16 + g;
        #pragma unroll
        for (int nt = 0; nt < 4; nt++){
            const int col = n0 + warpN + nt*8 + 2*t4;
            const float bv0 = ga.bias[col], bv1 = ga.bias[col+1];
            float a0 = acc[mt][nt][0] + bv0, a1 = acc[mt][nt][1] + bv1;
            float a2 = acc[mt][nt][2] + bv0, a3 = acc[mt][nt][3] + bv1;
            if (OMODE == 1){
                a0 *= ga.scale; a1 *= ga.scale; a2 *= ga.scale; a3 *= ga.scale;
                *(unsigned*)(ga.Cf + (size_t)row    *N + col) = pack2h(a0, a1);
                *(unsigned*)(ga.Cf + (size_t)(row+8)*N + col) = pack2h(a2, a3);
            } else {
                *(float2*)(ga.C + (size_t)row    *N + col) = make_float2(a0, a1);
                *(float2*)(ga.C + (size_t)(row+8)*N + col) = make_float2(a2, a3);
            }
        }
    }
}

__global__ __launch_bounds__(256, 2) void gemm3s_qkv(
    GemmArgs a0, GemmArgs a1, GemmArgs a2, int M, int N, int K)
{
    const GemmArgs& ga = (blockIdx.z == 0) ? a0 : (blockIdx.z == 1) ? a1 : a2;
    gemm3s_body<1>(ga, M, N, K);
}
__global__ __launch_bounds__(256, 2) void gemm3s_out(
    GemmArgs ga, int M, int N, int K)
{
    gemm3s_body<0>(ga, M, N, K);
}

// ---------------------------------------------------------------------------
// FP16 flash attention (single-term). Block = 128 q-rows of one (b,h);
// 8 warps x 16 rows; 64 keys/iter; cp.async 2-stage K/V pipeline; P in regs.
// Q pre-scaled by 1/sqrt(dk) at projection time. Output: bf16 hi/lo planes.
// ---------------------------------------------------------------------------
#define AS   72                 // fp16 elems per smem row (144B)
#define ATE  (64*AS)            // one K or V plane (4608)
#define ASTG (2*ATE)            // stage: K|V (9216)
#define QPL  (128*AS)           // transient Q plane (9216)

__global__ __launch_bounds__(256, 2) void attn_mma(
    const __half* __restrict__ Qf_g, const __half* __restrict__ Kf_g,
    const __half* __restrict__ Vf_g,
    __nv_bfloat16* __restrict__ Oh_g, __nv_bfloat16* __restrict__ Ol_g)
{
    extern __shared__ __half sh[];
    const int tid  = threadIdx.x;
    const int warp = tid >> 5, lane = tid & 31;
    const int g = lane >> 2, t4 = lane & 3;
    const int lr = lane & 7, grp = lane >> 3;
    const int qb = (int)gridDim.x - 1 - (int)blockIdx.x;   // long blocks first
    const int h = blockIdx.y, b = blockIdx.z;
    const int w16 = warp * 16;
    const int qrow0 = qb * 128;
    const size_t hoff = (size_t)h * DKH;

    // ---- Q tile (128 rows) -> transient smem, then fragments ----
    #pragma unroll
    for (int j = 0; j < 4; j++){
        const int cc = j*256 + tid;            // 1024 chunks
        const int r = cc >> 3, col = (cc & 7) * 8;
        cp16(sh + r*AS + col,
             Qf_g + (size_t)(b*SEQ + qrow0 + r)*DM + hoff + col);
    }
    cpcommit(); cpwait<0>();
    __syncthreads();

    unsigned qf[4][4];
    #pragma unroll
    for (int kc = 0; kc < 4; kc++){
        const int off = (w16 + lr + (grp&1)*8)*AS + kc*16 + (grp>>1)*8;
        ldsm4(qf[kc], sh + off);
    }
    __syncthreads();   // all warps done with Q smem before K/V overwrite

    auto issue = [&](int kt){
        const int st = (kt & 1) * ASTG;
        #pragma unroll
        for (int pl = 0; pl < 2; pl++){
            const __half* base = pl ? Vf_g : Kf_g;
            #pragma unroll
            for (int j = 0; j < 2; j++){
                const int cc = j*256 + tid;    // 512 chunks per plane
                const int r = cc >> 3, col = (cc & 7) * 8;
                cp16(sh + st + pl*ATE + r*AS + col,
                     base + (size_t)(b*SEQ + kt*64 + r)*DM + hoff + col);
            }
        }
        cpcommit();
    };

    float o[8][4];
    #pragma unroll
    for (int nn=0;nn<8;nn++)
        #pragma unroll
        for (int c=0;c<4;c++) o[nn][c] = 0.f;
    float mrow0 = -1e30f, mrow1 = -1e30f, lrow0 = 0.f, lrow1 = 0.f;

    const int nkt = 2*qb + 2;   // key tiles of 64 covering [0, qrow0+128)
    issue(0);
    for (int kt = 0; kt < nkt; kt++){
        if (kt + 1 < nkt){ issue(kt+1); cpwait<1>(); } else cpwait<0>();
        __syncthreads();

        const __half* Ks = sh + (kt & 1) * ASTG;
        const __half* Vs = Ks + ATE;

        // ---- S = Q K^T (fp16 single-term) ----
        float s[8][4];
        #pragma unroll
        for (int nn=0;nn<8;nn++)
            #pragma unroll
            for (int c=0;c<4;c++) s[nn][c] = 0.f;

        #pragma unroll
        for (int kc = 0; kc < 4; kc++){
            #pragma unroll
            for (int ng = 0; ng < 4; ng++){
                unsigned k4[4];
                const int off = (ng*16 + lr + (grp>>1)*8)*AS + kc*16 + (grp&1)*8;
                ldsm4(k4, Ks + off);
                mma16h(s[ng*2  ], qf[kc], k4[0], k4[1]);
                mma16h(s[ng*2+1], qf[kc], k4[2], k4[3]);
            }
        }

        // ---- causal mask (only tiles crossing this warp's diagonal) ----
        if (kt*64 + 63 > qrow0 + w16){
            const int r0 = qrow0 + w16 + g;
            #pragma unroll
            for (int nn = 0; nn < 8; nn++){
                const int col = kt*64 + nn*8 + 2*t4;
                if (col     > r0    ) s[nn][0] = -1e30f;
                if (col + 1 > r0    ) s[nn][1] = -1e30f;
                if (col     > r0 + 8) s[nn][2] = -1e30f;
                if (col + 1 > r0 + 8) s[nn][3] = -1e30f;
            }
        }

        // ---- online softmax ----
        float mx0 = -1e30f, mx1 = -1e30f;
        #pragma unroll
        for (int nn = 0; nn < 8; nn++){
            mx0 = fmaxf(mx0, fmaxf(s[nn][0], s[nn][1]));
            mx1 = fmaxf(mx1, fmaxf(s[nn][2], s[nn][3]));
        }
        mx0 = fmaxf(mx0, __shfl_xor_sync(0xffffffffu, mx0, 1));
        mx0 = fmaxf(mx0, __shfl_xor_sync(0xffffffffu, mx0, 2));
        mx1 = fmaxf(mx1, __shfl_xor_sync(0xffffffffu, mx1, 1));
        mx1 = fmaxf(mx1, __shfl_xor_sync(0xffffffffu, mx1, 2));

        const float mn0 = fmaxf(mrow0, mx0), mn1 = fmaxf(mrow1, mx1);
        const float cr0 = __expf(mrow0 - mn0), cr1 = __expf(mrow1 - mn1);
        lrow0 *= cr0; lrow1 *= cr1;
        #pragma unroll
        for (int nn = 0; nn < 8; nn++){
            o[nn][0] *= cr0; o[nn][1] *= cr0;
            o[nn][2] *= cr1; o[nn][3] *= cr1;
        }
        mrow0 = mn0; mrow1 = mn1;

        #pragma unroll
        for (int nn = 0; nn < 8; nn++){
            const float p0 = __expf(s[nn][0] - mn0);
            const float p1 = __expf(s[nn][1] - mn0);
            const float p2 = __expf(s[nn][2] - mn1);
            const float p3 = __expf(s[nn][3] - mn1);
            lrow0 += p0 + p1;
            lrow1 += p2 + p3;
            s[nn][0] = p0; s[nn][1] = p1; s[nn][2] = p2; s[nn][3] = p3;
        }

        // ---- O += P V (P fp16 in regs, V via ldmatrix.trans) ----
        #pragma unroll
        for (int kc = 0; kc < 4; kc++){
            const float* sA = s[2*kc];
            const float* sB = s[2*kc+1];
            unsigned p4[4];
            p4[0] = pack2h(sA[0], sA[1]);
            p4[1] = pack2h(sA[2], sA[3]);
            p4[2] = pack2h(sB[0], sB[1]);
            p4[3] = pack2h(sB[2], sB[3]);
            #pragma unroll
            for (int dt = 0; dt < 4; dt++){
                unsigned v4[4];
                const int off = (kc*16 + lr + (grp&1)*8)*AS + dt*16 + (grp>>1)*8;
                ldsm4t(v4, Vs + off);
                mma16h(o[dt*2  ], p4, v4[0], v4[1]);
                mma16h(o[dt*2+1], p4, v4[2], v4[3]);
            }
        }
        __syncthreads();   // all warps done reading this stage
    }

    // ---- final normalize + bf16 hi/lo split-store ----
    lrow0 += __shfl_xor_sync(0xffffffffu, lrow0, 1);
    lrow0 += __shfl_xor_sync(0xffffffffu, lrow0, 2);
    lrow1 += __shfl_xor_sync(0xffffffffu, lrow1, 1);
    lrow1 += __shfl_xor_sync(0xffffffffu, lrow1, 2);
    const float inv0 = 1.f / lrow0, inv1 = 1.f / lrow1;

    const int rowg = b*SEQ + qrow0 + w16 + g;
    const size_t base0 = (size_t)rowg    *DM + hoff;
    const size_t base1 = (size_t)(rowg+8)*DM + hoff;
    #pragma unroll
    for (int nn = 0; nn < 8; nn++){
        const int col = nn*8 + 2*t4;
        const float a0 = o[nn][0]*inv0, a1 = o[nn][1]*inv0;
        const float a2 = o[nn][2]*inv1, a3 = o[nn][3]*inv1;
        unsigned hw0 = pack2(a0, a1);
        unsigned lw0 = pack2(a0 - __uint_as_float(hw0 << 16),
                             a1 - __uint_as_float(hw0 & 0xffff0000u));
        unsigned hw1 = pack2(a2, a3);
        unsigned lw1 = pack2(a2 - __uint_as_float(hw1 << 16),
                             a3 - __uint_as_float(hw1 & 0xffff0000u));
        *(unsigned*)(Oh_g + base0 + col) = hw0;
        *(unsigned*)(Ol_g + base0 + col) = lw0;
        *(unsigned*)(Oh_g + base1 + col) = hw1;
        *(unsigned*)(Ol_g + base1 + col) = lw1;
    }
}

// ---------------------------------------------------------------------------
extern "C" void kernel_launch(void* const* d_in, const int* in_sizes, int n_in,
                              void* d_out, int out_size)
{
    const float* q   = (const float*)d_in[0];
    const float* k   = (const float*)d_in[1];
    const float* v   = (const float*)d_in[2];
    // d_in[3]: causal mask (tril) — computed analytically in-kernel.
    const float* w_q = (const float*)d_in[4];
    const float* b_q = (const float*)d_in[5];
    const float* w_k = (const float*)d_in[6];
    const float* b_k = (const float*)d_in[7];
    const float* w_v = (const float*)d_in[8];
    const float* b_v = (const float*)d_in[9];
    const float* w_o = (const float*)d_in[10];
    const float* b_o = (const float*)d_in[11];
    float* out = (float*)d_out;

    __nv_bfloat16 *aqh,*aql,*akh,*akl,*avh,*avl;
    __nv_bfloat16 *wqh,*wql,*wkh,*wkl,*wvh,*wvl,*woh,*wol;
    __nv_bfloat16 *Oh,*Ol;
    __half *Qf,*Kf,*Vf;
    cudaGetSymbolAddress((void**)&aqh, g_aqh); cudaGetSymbolAddress((void**)&aql, g_aql);
    cudaGetSymbolAddress((void**)&akh, g_akh); cudaGetSymbolAddress((void**)&akl, g_akl);
    cudaGetSymbolAddress((void**)&avh, g_avh); cudaGetSymbolAddress((void**)&avl, g_avl);
    cudaGetSymbolAddress((void**)&wqh, g_wqh); cudaGetSymbolAddress((void**)&wql, g_wql);
    cudaGetSymbolAddress((void**)&wkh, g_wkh); cudaGetSymbolAddress((void**)&wkl, g_wkl);
    cudaGetSymbolAddress((void**)&wvh, g_wvh); cudaGetSymbolAddress((void**)&wvl, g_wvl);
    cudaGetSymbolAddress((void**)&woh, g_woh); cudaGetSymbolAddress((void**)&wol, g_wol);
    cudaGetSymbolAddress((void**)&Qf,  g_Qf ); cudaGetSymbolAddress((void**)&Kf,  g_Kf );
    cudaGetSymbolAddress((void**)&Vf,  g_Vf );
    cudaGetSymbolAddress((void**)&Oh,  g_Oh ); cudaGetSymbolAddress((void**)&Ol,  g_Ol );

    const int gemm_smem = 2 * GSTG * (int)sizeof(__nv_bfloat16);   // 81920
    const int attn_smem = 2 * ASTG * (int)sizeof(__half);          // 36864
    cudaFuncSetAttribute(gemm3s_qkv, cudaFuncAttributeMaxDynamicSharedMemorySize, gemm_smem);
    cudaFuncSetAttribute(gemm3s_out, cudaFuncAttributeMaxDynamicSharedMemorySize, gemm_smem);
    cudaFuncSetAttribute(attn_mma,   cudaFuncAttributeMaxDynamicSharedMemorySize, attn_smem);

    // ---- pre-split inputs + weights (4 float4 per thread) ----
    const int n4i = NELEM / 4, n4w = WELEM / 4;
    const int bi = n4i / (256*4), bw = n4w / (256*4);
    split_planes<<<bi, 256>>>((const float4*)q,   (uint2*)aqh, (uint2*)aql, n4i);
    split_planes<<<bi, 256>>>((const float4*)k,   (uint2*)akh, (uint2*)akl, n4i);
    split_planes<<<bi, 256>>>((const float4*)v,   (uint2*)avh, (uint2*)avl, n4i);
    split_planes<<<bw, 256>>>((const float4*)w_q, (uint2*)wqh, (uint2*)wql, n4w);
    split_planes<<<bw, 256>>>((const float4*)w_k, (uint2*)wkh, (uint2*)wkl, n4w);
    split_planes<<<bw, 256>>>((const float4*)w_v, (uint2*)wvh, (uint2*)wvl, n4w);
    split_planes<<<bw, 256>>>((const float4*)w_o, (uint2*)woh, (uint2*)wol, n4w);

    // ---- fused QKV projections (fp16 outputs; Q pre-scaled by 1/8) ----
    GemmArgs gq = {aqh, aql, wqh, wql, b_q, nullptr, Qf, 0.125f};
    GemmArgs gk = {akh, akl, wkh, wkl, b_k, nullptr, Kf, 1.0f};
    GemmArgs gv = {avh, avl, wvh, wvl, b_v, nullptr, Vf, 1.0f};
    dim3 ggrid(DM / 128, MROWS / 128, 3);   // (8, 64, 3)
    gemm3s_qkv<<<ggrid, 256, gemm_smem>>>(gq, gk, gv, MROWS, DM, DM);

    dim3 agrid(SEQ / 128, NH, BATCH);       // (16, 16, 4)
    attn_mma<<<agrid, 256, attn_smem>>>(Qf, Kf, Vf, Oh, Ol);

    GemmArgs go = {Oh, Ol, woh, wol, b_o, out, nullptr, 1.0f};
    dim3 ogrid(DM / 128, MROWS / 128, 1);
    gemm3s_out<<<ogrid, 256, gemm_smem>>>(go, MROWS, DM, DM);
}

// round 14
// speedup vs baseline: 8.8415x; 1.3238x over previous
#include <cuda_runtime.h>
#include <cuda_fp16.h>

#define BATCH 4
#define SEQ   2048
#define DM    1024
#define NH    16
#define DKH   64
#define MROWS (BATCH*SEQ)      // 8192
#define NELEM (MROWS*DM)       // 8388608
#define WELEM (DM*DM)          // 1048576

// ---------------------------------------------------------------------------
// Scratch planes (device globals: allocation-free per harness rules)
// ---------------------------------------------------------------------------
__device__ __half g_xq[NELEM], g_xk[NELEM], g_xv[NELEM];   // fp16 inputs
__device__ __half g_wqh[WELEM], g_wql[WELEM];              // fp16 hi/lo of w*1024
__device__ __half g_wkh[WELEM], g_wkl[WELEM];
__device__ __half g_wvh[WELEM], g_wvl[WELEM];
__device__ __half g_woh[WELEM], g_wol[WELEM];
__device__ __half g_Qf[NELEM], g_Kf[NELEM], g_Vf[NELEM];   // projected (Q pre-scaled)
__device__ __half g_Of[NELEM];                             // attention output

// ---------------------------------------------------------------------------
// helpers
// ---------------------------------------------------------------------------
__device__ __forceinline__ unsigned pack2h(float e0, float e1){
    unsigned r; asm("cvt.rn.f16x2.f32 %0, %1, %2;" : "=r"(r) : "f"(e1), "f"(e0));
    return r;   // lo half = f16(e0), hi half = f16(e1)
}
__device__ __forceinline__ void mma16h(float c[4], const unsigned a[4],
                                       unsigned b0, unsigned b1){
    asm volatile("mma.sync.aligned.m16n8k16.row.col.f32.f16.f16.f32 "
        "{%0,%1,%2,%3},{%4,%5,%6,%7},{%8,%9},{%0,%1,%2,%3};\n"
        : "+f"(c[0]),"+f"(c[1]),"+f"(c[2]),"+f"(c[3])
        : "r"(a[0]),"r"(a[1]),"r"(a[2]),"r"(a[3]),"r"(b0),"r"(b1));
}
__device__ __forceinline__ void ldsm4(unsigned r[4], const void* p){
    unsigned addr = (unsigned)__cvta_generic_to_shared(p);
    asm volatile("ldmatrix.sync.aligned.m8n8.x4.shared.b16 {%0,%1,%2,%3},[%4];"
        : "=r"(r[0]),"=r"(r[1]),"=r"(r[2]),"=r"(r[3]) : "r"(addr));
}
__device__ __forceinline__ void ldsm4t(unsigned r[4], const void* p){
    unsigned addr = (unsigned)__cvta_generic_to_shared(p);
    asm volatile("ldmatrix.sync.aligned.m8n8.x4.trans.shared.b16 {%0,%1,%2,%3},[%4];"
        : "=r"(r[0]),"=r"(r[1]),"=r"(r[2]),"=r"(r[3]) : "r"(addr));
}
__device__ __forceinline__ void cp16(const void* smem_dst, const void* gmem_src){
    unsigned d = (unsigned)__cvta_generic_to_shared(smem_dst);
    asm volatile("cp.async.cg.shared.global [%0],[%1],16;" :: "r"(d), "l"(gmem_src));
}
__device__ __forceinline__ void cpcommit(){ asm volatile("cp.async.commit_group;"); }
template<int N> __device__ __forceinline__ void cpwait(){
    asm volatile("cp.async.wait_group %0;" :: "n"(N));
}

// ---------------------------------------------------------------------------
// input convert: fp32 -> fp16 (one kernel, grid.z picks array)
// ---------------------------------------------------------------------------
__global__ __launch_bounds__(256) void conv_f16(
    const float4* __restrict__ s0, const float4* __restrict__ s1,
    const float4* __restrict__ s2,
    uint2* __restrict__ d0, uint2* __restrict__ d1, uint2* __restrict__ d2,
    int n4)
{
    const float4* src = (blockIdx.z==0)?s0:(blockIdx.z==1)?s1:s2;
    uint2* dst = (blockIdx.z==0)?d0:(blockIdx.z==1)?d1:d2;
    const int base = blockIdx.x * (blockDim.x * 4) + threadIdx.x;
    #pragma unroll
    for (int j = 0; j < 4; j++){
        const int i = base + j * blockDim.x;
        if (i < n4){
            float4 v = src[i];
            dst[i] = make_uint2(pack2h(v.x, v.y), pack2h(v.z, v.w));
        }
    }
}

// ---------------------------------------------------------------------------
// weight split: fp16 hi/lo planes of (w * 1024)  (grid.z picks weight)
// ---------------------------------------------------------------------------
__global__ __launch_bounds__(256) void split_w(
    const float4* __restrict__ s0, const float4* __restrict__ s1,
    const float4* __restrict__ s2, const float4* __restrict__ s3,
    uint2* __restrict__ h0, uint2* __restrict__ h1,
    uint2* __restrict__ h2, uint2* __restrict__ h3,
    uint2* __restrict__ l0, uint2* __restrict__ l1,
    uint2* __restrict__ l2, uint2* __restrict__ l3,
    int n4)
{
    const int z = blockIdx.z;
    const float4* src = (z==0)?s0:(z==1)?s1:(z==2)?s2:s3;
    uint2* hi = (z==0)?h0:(z==1)?h1:(z==2)?h2:h3;
    uint2* lo = (z==0)?l0:(z==1)?l1:(z==2)?l2:l3;
    const int base = blockIdx.x * (blockDim.x * 4) + threadIdx.x;
    #pragma unroll
    for (int j = 0; j < 4; j++){
        const int i = base + j * blockDim.x;
        if (i < n4){
            float4 v = src[i];
            const float sx = v.x*1024.f, sy = v.y*1024.f;
            const float sz = v.z*1024.f, sw = v.w*1024.f;
            const float hx = __half2float(__float2half_rn(sx));
            const float hy = __half2float(__float2half_rn(sy));
            const float hz = __half2float(__float2half_rn(sz));
            const float hw = __half2float(__float2half_rn(sw));
            hi[i] = make_uint2(pack2h(hx, hy), pack2h(hz, hw));
            lo[i] = make_uint2(pack2h(sx-hx, sy-hy), pack2h(sz-hz, sw-hw));
        }
    }
}

// ---------------------------------------------------------------------------
// 2xFP16 GEMM: C[m,n] = (sum_k A[m,k]*Ws[n,k])/1024 + bias[n], Ws = w*1024
// split hi/lo. 128x128x32 tiles, 256 thr, 8 warps (64x32), cp.async 2-stage.
// OMODE 0: fp32 C.  OMODE 1: fp16 Cf, result scaled by ga.scale.
// ---------------------------------------------------------------------------
#define GS2  40                 // fp16 elems per smem row (80B)
#define GPL  (128*GS2)          // elems per plane (5120)
#define GSTG (3*GPL)            // stage: Af|Bh|Bl (15360)

struct GemmArgs {
    const __half *Af, *Bh, *Bl;
    const float* bias;
    float* C;
    __half* Cf;
    float scale;
};

template<int OMODE>
__device__ __forceinline__ void gemm2h_body(const GemmArgs& ga, int M, int N, int K)
{
    extern __shared__ __half smh[];
    const int tid  = threadIdx.x;
    const int warp = tid >> 5, lane = tid & 31;
    const int g = lane >> 2, t4 = lane & 3;
    const int lr = lane & 7, grp = lane >> 3;
    const int warpM = (warp >> 2) * 64;
    const int warpN = (warp & 3) * 32;
    const int m0 = blockIdx.y * 128, n0 = blockIdx.x * 128;

    float acc[4][4][4];
    #pragma unroll
    for (int i=0;i<4;i++)
        #pragma unroll
        for (int j=0;j<4;j++)
            #pragma unroll
            for (int c=0;c<4;c++) acc[i][j][c] = 0.f;

    auto issue = [&](int kt){
        const int st = (kt & 1) * GSTG;
        #pragma unroll
        for (int pl = 0; pl < 3; pl++){
            const __half* base = (pl==0)?ga.Af:(pl==1)?ga.Bh:ga.Bl;
            const int rb = (pl == 0) ? m0 : n0;
            #pragma unroll
            for (int j = 0; j < 2; j++){
                const int cc = j*256 + tid;
                const int r = cc >> 2, col = (cc & 3) * 8;
                cp16(smh + st + pl*GPL + r*GS2 + col,
                     base + (size_t)(rb + r)*K + kt*32 + col);
            }
        }
        cpcommit();
    };

    const int KT = K >> 5;
    issue(0);

    for (int kt = 0; kt < KT; kt++){
        if (kt + 1 < KT){ issue(kt+1); cpwait<1>(); } else cpwait<0>();
        __syncthreads();

        const __half* S   = smh + (kt & 1) * GSTG;
        const __half* SAf = S;
        const __half* SBh = S +     GPL;
        const __half* SBl = S + 2 * GPL;

        #pragma unroll
        for (int kc = 0; kc < 2; kc++){
            unsigned bh[2][4], bl[2][4];
            #pragma unroll
            for (int ng = 0; ng < 2; ng++){
                const int off = (warpN + ng*16 + lr + (grp>>1)*8)*GS2 + kc*16 + (grp&1)*8;
                ldsm4(bh[ng], SBh + off);
                ldsm4(bl[ng], SBl + off);
            }
            #pragma unroll
            for (int mt = 0; mt < 4; mt++){
                const int off = (warpM + mt*16 + lr + (grp&1)*8)*GS2 + kc*16 + (grp>>1)*8;
                unsigned af[4];
                ldsm4(af, SAf + off);
                #pragma unroll
                for (int ng = 0; ng < 2; ng++)
                    #pragma unroll
                    for (int hf = 0; hf < 2; hf++){
                        const int nt = ng*2 + hf;
                        mma16h(acc[mt][nt], af, bh[ng][2*hf], bh[ng][2*hf+1]);
                        mma16h(acc[mt][nt], af, bl[ng][2*hf], bl[ng][2*hf+1]);
                    }
            }
        }
        __syncthreads();
    }

    const float inv1024 = 1.f/1024.f;
    #pragma unroll
    for (int mt = 0; mt < 4; mt++){
        const int row = m0 + warpM + mt*16 + g;
        #pragma unroll
        for (int nt = 0; nt < 4; nt++){
            const int col = n0 + warpN + nt*8 + 2*t4;
            const float bv0 = ga.bias[col], bv1 = ga.bias[col+1];
            float a0 = acc[mt][nt][0]*inv1024 + bv0, a1 = acc[mt][nt][1]*inv1024 + bv1;
            float a2 = acc[mt][nt][2]*inv1024 + bv0, a3 = acc[mt][nt][3]*inv1024 + bv1;
            if (OMODE == 1){
                a0 *= ga.scale; a1 *= ga.scale; a2 *= ga.scale; a3 *= ga.scale;
                *(unsigned*)(ga.Cf + (size_t)row    *N + col) = pack2h(a0, a1);
                *(unsigned*)(ga.Cf + (size_t)(row+8)*N + col) = pack2h(a2, a3);
            } else {
                *(float2*)(ga.C + (size_t)row    *N + col) = make_float2(a0, a1);
                *(float2*)(ga.C + (size_t)(row+8)*N + col) = make_float2(a2, a3);
            }
        }
    }
}

__global__ __launch_bounds__(256, 2) void gemm2h_qkv(
    GemmArgs a0, GemmArgs a1, GemmArgs a2, int M, int N, int K)
{
    const GemmArgs& ga = (blockIdx.z == 0) ? a0 : (blockIdx.z == 1) ? a1 : a2;
    gemm2h_body<1>(ga, M, N, K);
}
__global__ __launch_bounds__(256, 2) void gemm2h_out(
    GemmArgs ga, int M, int N, int K)
{
    gemm2h_body<0>(ga, M, N, K);
}

// ---------------------------------------------------------------------------
// FP16 flash attention (single-term). Block = 128 q-rows of one (b,h);
// 8 warps x 16 rows; 64 keys/iter; cp.async 2-stage K/V pipeline; P in regs.
// Q pre-scaled by 1/sqrt(dk). Output: single fp16 plane.
// ---------------------------------------------------------------------------
#define AS   72                 // fp16 elems per smem row (144B)
#define ATE  (64*AS)            // one K or V plane (4608)
#define ASTG (2*ATE)            // stage: K|V (9216)

__global__ __launch_bounds__(256, 2) void attn_mma(
    const __half* __restrict__ Qf_g, const __half* __restrict__ Kf_g,
    const __half* __restrict__ Vf_g, __half* __restrict__ Of_g)
{
    extern __shared__ __half sh[];
    const int tid  = threadIdx.x;
    const int warp = tid >> 5, lane = tid & 31;
    const int g = lane >> 2, t4 = lane & 3;
    const int lr = lane & 7, grp = lane >> 3;
    const int qb = (int)gridDim.x - 1 - (int)blockIdx.x;   // long blocks first
    const int h = blockIdx.y, b = blockIdx.z;
    const int w16 = warp * 16;
    const int qrow0 = qb * 128;
    const size_t hoff = (size_t)h * DKH;

    // ---- Q tile (128 rows) -> transient smem, then fragments ----
    #pragma unroll
    for (int j = 0; j < 4; j++){
        const int cc = j*256 + tid;            // 1024 chunks
        const int r = cc >> 3, col = (cc & 7) * 8;
        cp16(sh + r*AS + col,
             Qf_g + (size_t)(b*SEQ + qrow0 + r)*DM + hoff + col);
    }
    cpcommit(); cpwait<0>();
    __syncthreads();

    unsigned qf[4][4];
    #pragma unroll
    for (int kc = 0; kc < 4; kc++){
        const int off = (w16 + lr + (grp&1)*8)*AS + kc*16 + (grp>>1)*8;
        ldsm4(qf[kc], sh + off);
    }
    __syncthreads();   // all warps done with Q smem before K/V overwrite

    auto issue = [&](int kt){
        const int st = (kt & 1) * ASTG;
        #pragma unroll
        for (int pl = 0; pl < 2; pl++){
            const __half* base = pl ? Vf_g : Kf_g;
            #pragma unroll
            for (int j = 0; j < 2; j++){
                const int cc = j*256 + tid;    // 512 chunks per plane
                const int r = cc >> 3, col = (cc & 7) * 8;
                cp16(sh + st + pl*ATE + r*AS + col,
                     base + (size_t)(b*SEQ + kt*64 + r)*DM + hoff + col);
            }
        }
        cpcommit();
    };

    float o[8][4];
    #pragma unroll
    for (int nn=0;nn<8;nn++)
        #pragma unroll
        for (int c=0;c<4;c++) o[nn][c] = 0.f;
    float mrow0 = -1e30f, mrow1 = -1e30f, lrow0 = 0.f, lrow1 = 0.f;

    const int nkt = 2*qb + 2;   // key tiles of 64 covering [0, qrow0+128)
    issue(0);
    for (int kt = 0; kt < nkt; kt++){
        if (kt + 1 < nkt){ issue(kt+1); cpwait<1>(); } else cpwait<0>();
        __syncthreads();

        const __half* Ks = sh + (kt & 1) * ASTG;
        const __half* Vs = Ks + ATE;

        // ---- S = Q K^T ----
        float s[8][4];
        #pragma unroll
        for (int nn=0;nn<8;nn++)
            #pragma unroll
            for (int c=0;c<4;c++) s[nn][c] = 0.f;

        #pragma unroll
        for (int kc = 0; kc < 4; kc++){
            #pragma unroll
            for (int ng = 0; ng < 4; ng++){
                unsigned k4[4];
                const int off = (ng*16 + lr + (grp>>1)*8)*AS + kc*16 + (grp&1)*8;
                ldsm4(k4, Ks + off);
                mma16h(s[ng*2  ], qf[kc], k4[0], k4[1]);
                mma16h(s[ng*2+1], qf[kc], k4[2], k4[3]);
            }
        }

        // ---- causal mask (only tiles crossing this warp's diagonal) ----
        if (kt*64 + 63 > qrow0 + w16){
            const int r0 = qrow0 + w16 + g;
            #pragma unroll
            for (int nn = 0; nn < 8; nn++){
                const int col = kt*64 + nn*8 + 2*t4;
                if (col     > r0    ) s[nn][0] = -1e30f;
                if (col + 1 > r0    ) s[nn][1] = -1e30f;
                if (col     > r0 + 8) s[nn][2] = -1e30f;
                if (col + 1 > r0 + 8) s[nn][3] = -1e30f;
            }
        }

        // ---- online softmax ----
        float mx0 = -1e30f, mx1 = -1e30f;
        #pragma unroll
        for (int nn = 0; nn < 8; nn++){
            mx0 = fmaxf(mx0, fmaxf(s[nn][0], s[nn][1]));
            mx1 = fmaxf(mx1, fmaxf(s[nn][2], s[nn][3]));
        }
        mx0 = fmaxf(mx0, __shfl_xor_sync(0xffffffffu, mx0, 1));
        mx0 = fmaxf(mx0, __shfl_xor_sync(0xffffffffu, mx0, 2));
        mx1 = fmaxf(mx1, __shfl_xor_sync(0xffffffffu, mx1, 1));
        mx1 = fmaxf(mx1, __shfl_xor_sync(0xffffffffu, mx1, 2));

        const float mn0 = fmaxf(mrow0, mx0), mn1 = fmaxf(mrow1, mx1);
        const float cr0 = __expf(mrow0 - mn0), cr1 = __expf(mrow1 - mn1);
        lrow0 *= cr0; lrow1 *= cr1;
        #pragma unroll
        for (int nn = 0; nn < 8; nn++){
            o[nn][0] *= cr0; o[nn][1] *= cr0;
            o[nn][2] *= cr1; o[nn][3] *= cr1;
        }
        mrow0 = mn0; mrow1 = mn1;

        #pragma unroll
        for (int nn = 0; nn < 8; nn++){
            const float p0 = __expf(s[nn][0] - mn0);
            const float p1 = __expf(s[nn][1] - mn0);
            const float p2 = __expf(s[nn][2] - mn1);
            const float p3 = __expf(s[nn][3] - mn1);
            lrow0 += p0 + p1;
            lrow1 += p2 + p3;
            s[nn][0] = p0; s[nn][1] = p1; s[nn][2] = p2; s[nn][3] = p3;
        }

        // ---- O += P V (P fp16 in regs, V via ldmatrix.trans) ----
        #pragma unroll
        for (int kc = 0; kc < 4; kc++){
            const float* sA = s[2*kc];
            const float* sB = s[2*kc+1];
            unsigned p4[4];
            p4[0] = pack2h(sA[0], sA[1]);
            p4[1] = pack2h(sA[2], sA[3]);
            p4[2] = pack2h(sB[0], sB[1]);
            p4[3] = pack2h(sB[2], sB[3]);
            #pragma unroll
            for (int dt = 0; dt < 4; dt++){
                unsigned v4[4];
                const int off = (kc*16 + lr + (grp&1)*8)*AS + dt*16 + (grp>>1)*8;
                ldsm4t(v4, Vs + off);
                mma16h(o[dt*2  ], p4, v4[0], v4[1]);
                mma16h(o[dt*2+1], p4, v4[2], v4[3]);
            }
        }
        __syncthreads();   // all warps done reading this stage
    }

    // ---- final normalize + fp16 store ----
    lrow0 += __shfl_xor_sync(0xffffffffu, lrow0, 1);
    lrow0 += __shfl_xor_sync(0xffffffffu, lrow0, 2);
    lrow1 += __shfl_xor_sync(0xffffffffu, lrow1, 1);
    lrow1 += __shfl_xor_sync(0xffffffffu, lrow1, 2);
    const float inv0 = 1.f / lrow0, inv1 = 1.f / lrow1;

    const int rowg = b*SEQ + qrow0 + w16 + g;
    const size_t base0 = (size_t)rowg    *DM + hoff;
    const size_t base1 = (size_t)(rowg+8)*DM + hoff;
    #pragma unroll
    for (int nn = 0; nn < 8; nn++){
        const int col = nn*8 + 2*t4;
        *(unsigned*)(Of_g + base0 + col) = pack2h(o[nn][0]*inv0, o[nn][1]*inv0);
        *(unsigned*)(Of_g + base1 + col) = pack2h(o[nn][2]*inv1, o[nn][3]*inv1);
    }
}

// ---------------------------------------------------------------------------
extern "C" void kernel_launch(void* const* d_in, const int* in_sizes, int n_in,
                              void* d_out, int out_size)
{
    const float* q   = (const float*)d_in[0];
    const float* k   = (const float*)d_in[1];
    const float* v   = (const float*)d_in[2];
    // d_in[3]: causal mask (tril) — computed analytically in-kernel.
    const float* w_q = (const float*)d_in[4];
    const float* b_q = (const float*)d_in[5];
    const float* w_k = (const float*)d_in[6];
    const float* b_k = (const float*)d_in[7];
    const float* w_v = (const float*)d_in[8];
    const float* b_v = (const float*)d_in[9];
    const float* w_o = (const float*)d_in[10];
    const float* b_o = (const float*)d_in[11];
    float* out = (float*)d_out;

    __half *xq,*xk,*xv, *wqh,*wql,*wkh,*wkl,*wvh,*wvl,*woh,*wol;
    __half *Qf,*Kf,*Vf,*Of;
    cudaGetSymbolAddress((void**)&xq,  g_xq ); cudaGetSymbolAddress((void**)&xk,  g_xk );
    cudaGetSymbolAddress((void**)&xv,  g_xv );
    cudaGetSymbolAddress((void**)&wqh, g_wqh); cudaGetSymbolAddress((void**)&wql, g_wql);
    cudaGetSymbolAddress((void**)&wkh, g_wkh); cudaGetSymbolAddress((void**)&wkl, g_wkl);
    cudaGetSymbolAddress((void**)&wvh, g_wvh); cudaGetSymbolAddress((void**)&wvl, g_wvl);
    cudaGetSymbolAddress((void**)&woh, g_woh); cudaGetSymbolAddress((void**)&wol, g_wol);
    cudaGetSymbolAddress((void**)&Qf,  g_Qf ); cudaGetSymbolAddress((void**)&Kf,  g_Kf );
    cudaGetSymbolAddress((void**)&Vf,  g_Vf ); cudaGetSymbolAddress((void**)&Of,  g_Of );

    const int gemm_smem = 2 * GSTG * (int)sizeof(__half);   // 61440
    const int attn_smem = 2 * ASTG * (int)sizeof(__half);   // 36864
    cudaFuncSetAttribute(gemm2h_qkv, cudaFuncAttributeMaxDynamicSharedMemorySize, gemm_smem);
    cudaFuncSetAttribute(gemm2h_out, cudaFuncAttributeMaxDynamicSharedMemorySize, gemm_smem);
    cudaFuncSetAttribute(attn_mma,   cudaFuncAttributeMaxDynamicSharedMemorySize, attn_smem);

    // ---- convert inputs to fp16 (one launch), split weights (one launch) ----
    const int n4i = NELEM / 4, n4w = WELEM / 4;
    dim3 cgrid(n4i / (256*4), 1, 3);
    conv_f16<<<cgrid, 256>>>((const float4*)q, (const float4*)k, (const float4*)v,
                             (uint2*)xq, (uint2*)xk, (uint2*)xv, n4i);
    dim3 wgrid(n4w / (256*4), 1, 4);
    split_w<<<wgrid, 256>>>((const float4*)w_q, (const float4*)w_k,
                            (const float4*)w_v, (const float4*)w_o,
                            (uint2*)wqh, (uint2*)wkh, (uint2*)wvh, (uint2*)woh,
                            (uint2*)wql, (uint2*)wkl, (uint2*)wvl, (uint2*)wol, n4w);

    // ---- fused QKV projections (fp16 outputs; Q pre-scaled by 1/8) ----
    GemmArgs gq = {xq, wqh, wql, b_q, nullptr, Qf, 0.125f};
    GemmArgs gk = {xk, wkh, wkl, b_k, nullptr, Kf, 1.0f};
    GemmArgs gv = {xv, wvh, wvl, b_v, nullptr, Vf, 1.0f};
    dim3 ggrid(DM / 128, MROWS / 128, 3);   // (8, 64, 3)
    gemm2h_qkv<<<ggrid, 256, gemm_smem>>>(gq, gk, gv, MROWS, DM, DM);

    dim3 agrid(SEQ / 128, NH, BATCH);       // (16, 16, 4)
    attn_mma<<<agrid, 256, attn_smem>>>(Qf, Kf, Vf, Of);

    GemmArgs go = {Of, woh, wol, b_o, out, nullptr, 1.0f};
    dim3 ogrid(DM / 128, MROWS / 128, 1);
    gemm2h_out<<<ogrid, 256, gemm_smem>>>(go, MROWS, DM, DM);
}